// round 4
// baseline (speedup 1.0000x reference)
#include <cuda_runtime.h>
#include <cuda_bf16.h>
#include <math.h>
#include <stdint.h>

// ---------------------------------------------------------------------------
// Problem constants
// ---------------------------------------------------------------------------
constexpr int NB   = 16;
constexpr int CH   = 512;
constexpr int NPIX = 1024;
constexpr int NGRP = 32;

// GEMM tiling: CTA 128x256, BK=32, 8 warps (2M x 4N), warp tile 64x64
constexpr int TM = 128, TN = 256, TK = 32;

constexpr int A_STAGE    = 16384;                   // 128 rows * 128B
constexpr int STAGE_BYTES = A_STAGE + TN * 128;     // + 256 rows * 128B = 49152
constexpr int NSTAGE     = 3;
constexpr int SPITCH     = 260;                     // fp32 epilogue pitch
constexpr int SMEM_BYTES = NSTAGE * STAGE_BYTES;    // 147456 (>= 128*260*4)

// ---------------------------------------------------------------------------
// Scratch (__device__ globals; allocation-free rule). hi/lo split-bf16 pairs.
// ---------------------------------------------------------------------------
#define BALIGN __align__(256)
__device__ BALIGN __nv_bfloat16 g_ht_h[(size_t)NB * NPIX * CH];
__device__ BALIGN __nv_bfloat16 g_ht_l[(size_t)NB * NPIX * CH];
__device__ BALIGN __nv_bfloat16 g_q_h [(size_t)NB * NPIX * CH];
__device__ BALIGN __nv_bfloat16 g_q_l [(size_t)NB * NPIX * CH];
__device__ BALIGN __nv_bfloat16 g_k_h [(size_t)NB * NPIX * CH];
__device__ BALIGN __nv_bfloat16 g_k_l [(size_t)NB * NPIX * CH];
__device__ BALIGN __nv_bfloat16 g_v_h [(size_t)NB * CH * NPIX];
__device__ BALIGN __nv_bfloat16 g_v_l [(size_t)NB * CH * NPIX];
__device__ BALIGN __nv_bfloat16 g_p_h [(size_t)NB * NPIX * NPIX];
__device__ BALIGN __nv_bfloat16 g_p_l [(size_t)NB * NPIX * NPIX];
__device__ BALIGN __nv_bfloat16 g_ot_h[(size_t)NB * NPIX * CH];
__device__ BALIGN __nv_bfloat16 g_ot_l[(size_t)NB * NPIX * CH];
__device__ BALIGN __nv_bfloat16 g_wq_h[(size_t)3 * CH * CH];
__device__ BALIGN __nv_bfloat16 g_wq_l[(size_t)3 * CH * CH];
__device__ BALIGN __nv_bfloat16 g_wp_h[(size_t)CH * CH];
__device__ BALIGN __nv_bfloat16 g_wp_l[(size_t)CH * CH];
__device__ BALIGN float         g_attn[(size_t)NB * NPIX * NPIX];
__device__ float g_stats[NB * NGRP * 2];

// ---------------------------------------------------------------------------
// helpers
// ---------------------------------------------------------------------------
__device__ __forceinline__ uint32_t smem_u32(const void* p) {
    uint32_t a;
    asm("{ .reg .u64 t; cvta.to.shared.u64 t, %1; cvt.u32.u64 %0, t; }" : "=r"(a) : "l"(p));
    return a;
}
__device__ __forceinline__ void split_bf16(float v, __nv_bfloat16& h, __nv_bfloat16& l) {
    h = __float2bfloat16(v);
    l = __float2bfloat16(v - __bfloat162float(h));
}

#define CP16(sm, gp) asm volatile("cp.async.cg.shared.global [%0], [%1], 16;" :: "r"(sm), "l"(gp))
#define CP_COMMIT()  asm volatile("cp.async.commit_group;" ::: "memory")
#define CP_WAIT0()   asm volatile("cp.async.wait_group 0;" ::: "memory")
#define CP_WAIT1()   asm volatile("cp.async.wait_group 1;" ::: "memory")

#define LDSM4(r0, r1, r2, r3, a) \
    asm volatile("ldmatrix.sync.aligned.m8n8.x4.shared.b16 {%0,%1,%2,%3}, [%4];" \
                 : "=r"(r0), "=r"(r1), "=r"(r2), "=r"(r3) : "r"(a))

#define MMA_BF16(d, a, b0, b1) \
    asm volatile("mma.sync.aligned.m16n8k16.row.col.f32.bf16.bf16.f32 " \
                 "{%0,%1,%2,%3},{%4,%5,%6,%7},{%8,%9},{%0,%1,%2,%3};" \
                 : "+f"((d)[0]), "+f"((d)[1]), "+f"((d)[2]), "+f"((d)[3]) \
                 : "r"((a)[0]), "r"((a)[1]), "r"((a)[2]), "r"((a)[3]), "r"(b0), "r"(b1))

// ---------------------------------------------------------------------------
// GroupNorm phase 1: per-(b,g) mean / rstd
// ---------------------------------------------------------------------------
__global__ __launch_bounds__(256) void gn_stats_kernel(
    const float* __restrict__ x, float* __restrict__ stats)
{
    const int GSZ = (CH / NGRP) * NPIX;
    const int bg  = blockIdx.x;
    const float4* xv = (const float4*)(x + (size_t)bg * GSZ);
    const int tid = threadIdx.x;

    float s = 0.f, ss = 0.f;
    for (int i = tid; i < GSZ / 4; i += 256) {
        float4 v = xv[i];
        s  += v.x + v.y + v.z + v.w;
        ss += v.x * v.x + v.y * v.y + v.z * v.z + v.w * v.w;
    }
    __shared__ float rs[256], rss[256];
    rs[tid] = s; rss[tid] = ss;
    __syncthreads();
    for (int o = 128; o > 0; o >>= 1) {
        if (tid < o) { rs[tid] += rs[tid + o]; rss[tid] += rss[tid + o]; }
        __syncthreads();
    }
    if (tid == 0) {
        float mu  = rs[0] / GSZ;
        float var = rss[0] / GSZ - mu * mu;
        stats[bg * 2]     = mu;
        stats[bg * 2 + 1] = rsqrtf(var + 1e-5f);
    }
}

// ---------------------------------------------------------------------------
// GroupNorm phase 2: normalize + split + transpose -> ht[b][p][c]
// ---------------------------------------------------------------------------
__global__ __launch_bounds__(256) void gn_apply_kernel(
    const float* __restrict__ x, const float* __restrict__ gamma,
    const float* __restrict__ beta, const float* __restrict__ stats,
    __nv_bfloat16* __restrict__ hth, __nv_bfloat16* __restrict__ htl)
{
    __shared__ float s[32][33];
    const int p0 = blockIdx.x * 32, c0 = blockIdx.y * 32, b = blockIdx.z;
    const int tid = threadIdx.x;

    #pragma unroll
    for (int q = 0; q < 4; q++) {
        int ci = (tid >> 5) + q * 8, pj = tid & 31;
        int c = c0 + ci;
        float xv = x[((size_t)b * CH + c) * NPIX + p0 + pj];
        int g = c >> 4;
        float mu = stats[(b * NGRP + g) * 2], rinv = stats[(b * NGRP + g) * 2 + 1];
        s[ci][pj] = (xv - mu) * rinv * gamma[c] + beta[c];
    }
    __syncthreads();
    #pragma unroll
    for (int q = 0; q < 4; q++) {
        int cj = tid & 31, pi = (tid >> 5) + q * 8;
        __nv_bfloat16 h, l;
        split_bf16(s[cj][pi], h, l);
        size_t o = (size_t)b * NPIX * CH + (size_t)(p0 + pi) * CH + c0 + cj;
        hth[o] = h; htl[o] = l;
    }
}

// ---------------------------------------------------------------------------
// Row softmax -> split-bf16 P
// ---------------------------------------------------------------------------
__global__ __launch_bounds__(256) void softmax_kernel(
    const float* __restrict__ attn,
    __nv_bfloat16* __restrict__ ph, __nv_bfloat16* __restrict__ pl)
{
    const size_t row = blockIdx.x;
    const float4* p = (const float4*)(attn + row * NPIX);
    const int tid = threadIdx.x;

    float4 v = p[tid];
    float m = fmaxf(fmaxf(v.x, v.y), fmaxf(v.z, v.w));

    __shared__ float red[256];
    red[tid] = m; __syncthreads();
    for (int o = 128; o > 0; o >>= 1) {
        if (tid < o) red[tid] = fmaxf(red[tid], red[tid + o]);
        __syncthreads();
    }
    const float rmax = red[0];
    __syncthreads();

    v.x = expf(v.x - rmax); v.y = expf(v.y - rmax);
    v.z = expf(v.z - rmax); v.w = expf(v.w - rmax);
    red[tid] = v.x + v.y + v.z + v.w; __syncthreads();
    for (int o = 128; o > 0; o >>= 1) {
        if (tid < o) red[tid] += red[tid + o];
        __syncthreads();
    }
    const float rinv = 1.f / red[0];
    float vals[4] = {v.x * rinv, v.y * rinv, v.z * rinv, v.w * rinv};
    __nv_bfloat16 hh[4], ll[4];
    #pragma unroll
    for (int i = 0; i < 4; i++) split_bf16(vals[i], hh[i], ll[i]);
    size_t o = row * NPIX + tid * 4;
    *(__nv_bfloat162*)(ph + o)     = __nv_bfloat162(hh[0], hh[1]);
    *(__nv_bfloat162*)(ph + o + 2) = __nv_bfloat162(hh[2], hh[3]);
    *(__nv_bfloat162*)(pl + o)     = __nv_bfloat162(ll[0], ll[1]);
    *(__nv_bfloat162*)(pl + o + 2) = __nv_bfloat162(ll[2], ll[3]);
}

// ---------------------------------------------------------------------------
// fp32 -> split-bf16 (weights)
// ---------------------------------------------------------------------------
__global__ __launch_bounds__(256) void pack_kernel(
    const float* __restrict__ w,
    __nv_bfloat16* __restrict__ oh, __nv_bfloat16* __restrict__ ol, int n)
{
    int i = (blockIdx.x * 256 + threadIdx.x) * 2;
    if (i < n) {
        __nv_bfloat16 h0, l0, h1, l1;
        split_bf16(w[i], h0, l0);
        split_bf16(w[i + 1], h1, l1);
        *(__nv_bfloat162*)(oh + i) = __nv_bfloat162(h0, h1);
        *(__nv_bfloat162*)(ol + i) = __nv_bfloat162(l0, l1);
    }
}

// ---------------------------------------------------------------------------
// Split-bf16 HMMA GEMM: D[m][n] = sum_k A[m][k]*B[n][k]  (both k-major)
// CTA 128x256, BK=32, 8 warps (2M x 4N), warp tile 64x64, 3-stage cp.async.
// smem row = 128B: [hi 32 bf16 | lo 32 bf16], 16B units XOR-swizzled by row&7.
// EPI 0: QKV  1: scores  2: PV  3: proj(+bias+residual)
// ---------------------------------------------------------------------------
template<int EPI>
__global__ __launch_bounds__(256, 1) void tc_gemm(
    const __nv_bfloat16* __restrict__ Agh, const __nv_bfloat16* __restrict__ Agl,
    const __nv_bfloat16* __restrict__ Bgh, const __nv_bfloat16* __restrict__ Bgl,
    long long sAb, long long sBb, int ldA, int ldB, int K,
    const float* __restrict__ bias, float scale,
    float* __restrict__ outf,
    __nv_bfloat16* __restrict__ o0h, __nv_bfloat16* __restrict__ o0l,
    __nv_bfloat16* __restrict__ o1h, __nv_bfloat16* __restrict__ o1l,
    __nv_bfloat16* __restrict__ o2h, __nv_bfloat16* __restrict__ o2l,
    const float* __restrict__ resid)
{
    extern __shared__ char smem[];
    const uint32_t sb = smem_u32(smem);
    const int tid = threadIdx.x;
    const int lane = tid & 31, wid = tid >> 5;
    const int bz = blockIdx.z;
    const int m0 = blockIdx.y * TM;
    const int n0 = blockIdx.x * TN;

    const __nv_bfloat16* Ah = Agh + (size_t)bz * sAb + (size_t)m0 * ldA;
    const __nv_bfloat16* Al = Agl + (size_t)bz * sAb + (size_t)m0 * ldA;
    const __nv_bfloat16* Bh = Bgh + (size_t)bz * sBb + (size_t)n0 * ldB;
    const __nv_bfloat16* Bl = Bgl + (size_t)bz * sBb + (size_t)n0 * ldB;

    // loaders: A: row = tid>>1 (0..127), 4 units (hi for even tid, lo for odd)
    //          B: row = tid (0..255), all 8 units
    const int ar_row = tid >> 1;
    const int ar_lo  = tid & 1;            // 0 = hi units 0-3, 1 = lo units 4-7

    auto load_tile = [&](int buf, int k0) {
        const uint32_t sa  = sb + buf * STAGE_BYTES;
        const uint32_t sbB = sa + A_STAGE;
        const __nv_bfloat16* Asrc = ar_lo ? Al : Ah;
        #pragma unroll
        for (int j = 0; j < 4; j++) {
            const int u = ar_lo * 4 + j;
            CP16(sa + ar_row * 128 + ((u ^ (ar_row & 7)) << 4),
                 Asrc + (size_t)ar_row * ldA + k0 + j * 8);
        }
        #pragma unroll
        for (int u = 0; u < 8; u++) {
            const __nv_bfloat16* Bsrc = (u < 4) ? Bh : Bl;
            const int kc = (u & 3) * 8;
            CP16(sbB + tid * 128 + ((u ^ (tid & 7)) << 4),
                 Bsrc + (size_t)tid * ldB + k0 + kc);
        }
    };

    // warp layout: 2 (M) x 4 (N); warp tile 64x64
    const int wm = wid >> 2, wn = wid & 3;
    const int m_base = wm * 64, n_base = wn * 64;

    // ldmatrix lane mapping
    const int amat = lane >> 3;
    const int arow = (amat & 1) * 8 + (lane & 7);
    const int auadd = amat >> 1;
    const int bmat = lane >> 3;
    const int bnrow = (bmat >> 1) * 8 + (lane & 7);
    const int buadd = bmat & 1;

    float acc[4][8][4] = {};

    load_tile(0, 0);
    CP_COMMIT();
    load_tile(1, TK);
    CP_COMMIT();

    const int nk = K / TK;
    for (int i = 0; i < nk; i++) {
        if (i == nk - 1) { CP_WAIT0(); } else { CP_WAIT1(); }
        __syncthreads();
        if (i + 2 < nk) {
            load_tile((i + 2) % NSTAGE, (i + 2) * TK);
            CP_COMMIT();
        }
        const uint32_t sa  = sb + (i % NSTAGE) * STAGE_BYTES;
        const uint32_t sbB = sa + A_STAGE;

        #pragma unroll
        for (int kk = 0; kk < 2; kk++) {
            uint32_t ah[4][4], al[4][4], bh[16], bl[16];
            #pragma unroll
            for (int mt = 0; mt < 4; mt++) {
                const int row = m_base + mt * 16 + arow;
                const int rx = row & 7;
                const uint32_t base = sa + row * 128;
                const int uh = kk * 2 + auadd;
                LDSM4(ah[mt][0], ah[mt][1], ah[mt][2], ah[mt][3], base + ((uh ^ rx) << 4));
                LDSM4(al[mt][0], al[mt][1], al[mt][2], al[mt][3], base + (((uh + 4) ^ rx) << 4));
            }
            #pragma unroll
            for (int np = 0; np < 4; np++) {
                const int n = n_base + np * 16 + bnrow;
                const int rx = n & 7;
                const uint32_t base = sbB + n * 128;
                const int uh = kk * 2 + buadd;
                LDSM4(bh[np * 4 + 0], bh[np * 4 + 1], bh[np * 4 + 2], bh[np * 4 + 3],
                      base + ((uh ^ rx) << 4));
                LDSM4(bl[np * 4 + 0], bl[np * 4 + 1], bl[np * 4 + 2], bl[np * 4 + 3],
                      base + (((uh + 4) ^ rx) << 4));
            }
            #pragma unroll
            for (int mt = 0; mt < 4; mt++) {
                #pragma unroll
                for (int nt = 0; nt < 8; nt++) {
                    const int r = (nt >> 1) * 4 + (nt & 1) * 2;
                    MMA_BF16(acc[mt][nt], ah[mt], bh[r], bh[r + 1]);
                    MMA_BF16(acc[mt][nt], ah[mt], bl[r], bl[r + 1]);
                    MMA_BF16(acc[mt][nt], al[mt], bh[r], bh[r + 1]);
                }
            }
        }
    }

    // ---- stage accumulators to smem fp32 (reuse pipeline smem) ----
    __syncthreads();
    float* s = (float*)smem;
    #pragma unroll
    for (int mt = 0; mt < 4; mt++)
        #pragma unroll
        for (int nt = 0; nt < 8; nt++)
            #pragma unroll
            for (int r = 0; r < 4; r++) {
                const int row = m_base + mt * 16 + (lane >> 2) + (r >= 2 ? 8 : 0);
                const int col = n_base + nt * 8 + (lane & 3) * 2 + (r & 1);
                s[row * SPITCH + col] = acc[mt][nt][r];
            }
    __syncthreads();

    // ---- writers (128 x 256 tile, 64 iterations of float2/bf162) ----
    if (EPI == 0 && m0 < 2 * CH) {
        // Q or K tile: [p][c] output, m-fast pairs for coalescing over c
        __nv_bfloat16* dh = (m0 < CH ? o0h : o1h) + (size_t)bz * NPIX * CH;
        __nv_bfloat16* dl = (m0 < CH ? o0l : o1l) + (size_t)bz * NPIX * CH;
        const int coff = m0 & (CH - 1);
        for (int it = 0; it < 64; it++) {
            const int idx = it * 512 + tid * 2;
            const int n = idx >> 7, m = idx & 127;
            float v0 = s[m * SPITCH + n] + bias[m0 + m];
            float v1 = s[(m + 1) * SPITCH + n] + bias[m0 + m + 1];
            __nv_bfloat16 h0, l0, h1, l1;
            split_bf16(v0, h0, l0); split_bf16(v1, h1, l1);
            const size_t o = (size_t)(n0 + n) * CH + coff + m;
            *(__nv_bfloat162*)(dh + o) = __nv_bfloat162(h0, h1);
            *(__nv_bfloat162*)(dl + o) = __nv_bfloat162(l0, l1);
        }
    } else {
        for (int it = 0; it < 64; it++) {
            const int idx = it * 512 + tid * 2;
            const int m = idx >> 8, n = idx & 255;
            float v0 = s[m * SPITCH + n];
            float v1 = s[m * SPITCH + n + 1];
            if (EPI == 0) {          // V tile -> v[b][c][p]
                const int c = m0 - 2 * CH + m;
                v0 += bias[m0 + m]; v1 += bias[m0 + m];
                __nv_bfloat16 h0, l0, h1, l1;
                split_bf16(v0, h0, l0); split_bf16(v1, h1, l1);
                const size_t o = ((size_t)bz * CH + c) * NPIX + n0 + n;
                *(__nv_bfloat162*)(o2h + o) = __nv_bfloat162(h0, h1);
                *(__nv_bfloat162*)(o2l + o) = __nv_bfloat162(l0, l1);
            } else if (EPI == 1) {   // scores fp32
                const size_t o = ((size_t)bz * NPIX + m0 + m) * NPIX + n0 + n;
                *(float2*)(outf + o) = make_float2(v0 * scale, v1 * scale);
            } else if (EPI == 2) {   // Ot split [p][c]
                __nv_bfloat16 h0, l0, h1, l1;
                split_bf16(v0, h0, l0); split_bf16(v1, h1, l1);
                const size_t o = ((size_t)bz * NPIX + m0 + m) * CH + n0 + n;
                *(__nv_bfloat162*)(o0h + o) = __nv_bfloat162(h0, h1);
                *(__nv_bfloat162*)(o0l + o) = __nv_bfloat162(l0, l1);
            } else {                 // proj + bias + residual
                const float bv = bias[m0 + m];
                const size_t o = ((size_t)bz * CH + m0 + m) * NPIX + n0 + n;
                float2 rv = *(const float2*)(resid + o);
                *(float2*)(outf + o) = make_float2(v0 + bv + rv.x, v1 + bv + rv.y);
            }
        }
    }
}

// ---------------------------------------------------------------------------
extern "C" void kernel_launch(void* const* d_in, const int* in_sizes, int n_in,
                              void* d_out, int out_size)
{
    const float* x      = (const float*)d_in[0];
    const float* gamma  = (const float*)d_in[1];
    const float* beta   = (const float*)d_in[2];
    const float* w_qkv  = (const float*)d_in[3];
    const float* b_qkv  = (const float*)d_in[4];
    const float* w_proj = (const float*)d_in[5];
    const float* b_proj = (const float*)d_in[6];
    float* out = (float*)d_out;

    __nv_bfloat16 *hth, *htl, *qh, *ql, *kh, *kl, *vh, *vl, *ph, *pl,
                  *oth, *otl, *wqh, *wql, *wph, *wpl;
    float *attn, *stats;
    cudaGetSymbolAddress((void**)&hth, g_ht_h); cudaGetSymbolAddress((void**)&htl, g_ht_l);
    cudaGetSymbolAddress((void**)&qh,  g_q_h ); cudaGetSymbolAddress((void**)&ql,  g_q_l );
    cudaGetSymbolAddress((void**)&kh,  g_k_h ); cudaGetSymbolAddress((void**)&kl,  g_k_l );
    cudaGetSymbolAddress((void**)&vh,  g_v_h ); cudaGetSymbolAddress((void**)&vl,  g_v_l );
    cudaGetSymbolAddress((void**)&ph,  g_p_h ); cudaGetSymbolAddress((void**)&pl,  g_p_l );
    cudaGetSymbolAddress((void**)&oth, g_ot_h); cudaGetSymbolAddress((void**)&otl, g_ot_l);
    cudaGetSymbolAddress((void**)&wqh, g_wq_h); cudaGetSymbolAddress((void**)&wql, g_wq_l);
    cudaGetSymbolAddress((void**)&wph, g_wp_h); cudaGetSymbolAddress((void**)&wpl, g_wp_l);
    cudaGetSymbolAddress((void**)&attn, g_attn);
    cudaGetSymbolAddress((void**)&stats, g_stats);

    cudaFuncSetAttribute(tc_gemm<0>, cudaFuncAttributeMaxDynamicSharedMemorySize, SMEM_BYTES);
    cudaFuncSetAttribute(tc_gemm<1>, cudaFuncAttributeMaxDynamicSharedMemorySize, SMEM_BYTES);
    cudaFuncSetAttribute(tc_gemm<2>, cudaFuncAttributeMaxDynamicSharedMemorySize, SMEM_BYTES);
    cudaFuncSetAttribute(tc_gemm<3>, cudaFuncAttributeMaxDynamicSharedMemorySize, SMEM_BYTES);

    const long long sH = (long long)NPIX * CH;
    const long long sP = (long long)NPIX * NPIX;

    pack_kernel<<<(3 * CH * CH / 2 + 255) / 256, 256>>>(w_qkv, wqh, wql, 3 * CH * CH);
    pack_kernel<<<(CH * CH / 2 + 255) / 256, 256>>>(w_proj, wph, wpl, CH * CH);
    gn_stats_kernel<<<NB * NGRP, 256>>>(x, stats);
    gn_apply_kernel<<<dim3(NPIX / 32, CH / 32, NB), 256>>>(x, gamma, beta, stats, hth, htl);

    // QKV: A = w_qkv [1536,512], B = ht[b][p][c] -> q/k [p][c], v [c][p]
    tc_gemm<0><<<dim3(NPIX / TN, 1536 / TM, NB), 256, SMEM_BYTES>>>(
        wqh, wql, hth, htl, 0, sH, CH, CH, CH,
        b_qkv, 1.f, nullptr, qh, ql, kh, kl, vh, vl, nullptr);

    // scores: q[i][c] . k[j][c] * scale -> attn fp32
    tc_gemm<1><<<dim3(NPIX / TN, NPIX / TM, NB), 256, SMEM_BYTES>>>(
        qh, ql, kh, kl, sH, sH, CH, CH, CH,
        nullptr, 1.0f / sqrtf((float)CH), attn,
        nullptr, nullptr, nullptr, nullptr, nullptr, nullptr, nullptr);

    softmax_kernel<<<NB * NPIX, 256>>>(attn, ph, pl);

    // PV: p[i][j] . v[c][j] -> ot[p][c]
    tc_gemm<2><<<dim3(CH / TN, NPIX / TM, NB), 256, SMEM_BYTES>>>(
        ph, pl, vh, vl, sP, sH, NPIX, NPIX, NPIX,
        nullptr, 1.f, nullptr, oth, otl,
        nullptr, nullptr, nullptr, nullptr, nullptr);

    // proj: w_proj[o][c] . ot[p][c] + bias + residual -> out [b][c][p]
    tc_gemm<3><<<dim3(NPIX / TN, CH / TM, NB), 256, SMEM_BYTES>>>(
        wph, wpl, oth, otl, 0, sH, CH, CH, CH,
        b_proj, 1.f, out, nullptr, nullptr, nullptr, nullptr, nullptr, nullptr, x);
}

// round 5
// speedup vs baseline: 1.2082x; 1.2082x over previous
#include <cuda_runtime.h>
#include <cuda_bf16.h>
#include <math.h>
#include <stdint.h>

// ---------------------------------------------------------------------------
// Problem constants
// ---------------------------------------------------------------------------
constexpr int NB   = 16;
constexpr int CH   = 512;
constexpr int NPIX = 1024;
constexpr int NGRP = 32;

// GEMM tiling: CTA 128x128, BK=32, 8 warps (2M x 4N), warp tile 64x32
constexpr int TM = 128, TN = 128, TK = 32;

constexpr int STAGE_BYTES = 32768;                  // A 16KB + B 16KB
constexpr int NSTAGE      = 3;
constexpr int SPITCH      = 129;                    // fp32 epilogue pitch
constexpr int SMEM_BYTES  = NSTAGE * STAGE_BYTES;   // 98304 (>= 128*129*4)

// ---------------------------------------------------------------------------
// Scratch (__device__ globals; allocation-free rule). hi/lo split-bf16 pairs.
// ---------------------------------------------------------------------------
#define BALIGN __align__(256)
__device__ BALIGN __nv_bfloat16 g_ht_h[(size_t)NB * NPIX * CH];
__device__ BALIGN __nv_bfloat16 g_ht_l[(size_t)NB * NPIX * CH];
__device__ BALIGN __nv_bfloat16 g_q_h [(size_t)NB * NPIX * CH];
__device__ BALIGN __nv_bfloat16 g_q_l [(size_t)NB * NPIX * CH];
__device__ BALIGN __nv_bfloat16 g_k_h [(size_t)NB * NPIX * CH];
__device__ BALIGN __nv_bfloat16 g_k_l [(size_t)NB * NPIX * CH];
__device__ BALIGN __nv_bfloat16 g_v_h [(size_t)NB * CH * NPIX];
__device__ BALIGN __nv_bfloat16 g_v_l [(size_t)NB * CH * NPIX];
__device__ BALIGN __nv_bfloat16 g_p_h [(size_t)NB * NPIX * NPIX];
__device__ BALIGN __nv_bfloat16 g_p_l [(size_t)NB * NPIX * NPIX];
__device__ BALIGN __nv_bfloat16 g_ot_h[(size_t)NB * NPIX * CH];
__device__ BALIGN __nv_bfloat16 g_ot_l[(size_t)NB * NPIX * CH];
__device__ BALIGN __nv_bfloat16 g_wq_h[(size_t)3 * CH * CH];
__device__ BALIGN __nv_bfloat16 g_wq_l[(size_t)3 * CH * CH];
__device__ BALIGN __nv_bfloat16 g_wp_h[(size_t)CH * CH];
__device__ BALIGN __nv_bfloat16 g_wp_l[(size_t)CH * CH];
__device__ BALIGN float         g_attn[(size_t)NB * NPIX * NPIX];
__device__ float g_stats[NB * NGRP * 2];

// ---------------------------------------------------------------------------
// helpers
// ---------------------------------------------------------------------------
__device__ __forceinline__ uint32_t smem_u32(const void* p) {
    uint32_t a;
    asm("{ .reg .u64 t; cvta.to.shared.u64 t, %1; cvt.u32.u64 %0, t; }" : "=r"(a) : "l"(p));
    return a;
}
__device__ __forceinline__ void split_bf16(float v, __nv_bfloat16& h, __nv_bfloat16& l) {
    h = __float2bfloat16(v);
    l = __float2bfloat16(v - __bfloat162float(h));
}

#define CP16(sm, gp) asm volatile("cp.async.cg.shared.global [%0], [%1], 16;" :: "r"(sm), "l"(gp))
#define CP_COMMIT()  asm volatile("cp.async.commit_group;" ::: "memory")
#define CP_WAIT0()   asm volatile("cp.async.wait_group 0;" ::: "memory")
#define CP_WAIT1()   asm volatile("cp.async.wait_group 1;" ::: "memory")

#define LDSM4(r0, r1, r2, r3, a) \
    asm volatile("ldmatrix.sync.aligned.m8n8.x4.shared.b16 {%0,%1,%2,%3}, [%4];" \
                 : "=r"(r0), "=r"(r1), "=r"(r2), "=r"(r3) : "r"(a))

#define MMA_BF16(d, a, b0, b1) \
    asm volatile("mma.sync.aligned.m16n8k16.row.col.f32.bf16.bf16.f32 " \
                 "{%0,%1,%2,%3},{%4,%5,%6,%7},{%8,%9},{%0,%1,%2,%3};" \
                 : "+f"((d)[0]), "+f"((d)[1]), "+f"((d)[2]), "+f"((d)[3]) \
                 : "r"((a)[0]), "r"((a)[1]), "r"((a)[2]), "r"((a)[3]), "r"(b0), "r"(b1))

// ---------------------------------------------------------------------------
// GroupNorm phase 1: per-(b,g) mean / rstd
// ---------------------------------------------------------------------------
__global__ __launch_bounds__(256) void gn_stats_kernel(
    const float* __restrict__ x, float* __restrict__ stats)
{
    const int GSZ = (CH / NGRP) * NPIX;
    const int bg  = blockIdx.x;
    const float4* xv = (const float4*)(x + (size_t)bg * GSZ);
    const int tid = threadIdx.x;

    float s = 0.f, ss = 0.f;
    for (int i = tid; i < GSZ / 4; i += 256) {
        float4 v = xv[i];
        s  += v.x + v.y + v.z + v.w;
        ss += v.x * v.x + v.y * v.y + v.z * v.z + v.w * v.w;
    }
    __shared__ float rs[256], rss[256];
    rs[tid] = s; rss[tid] = ss;
    __syncthreads();
    for (int o = 128; o > 0; o >>= 1) {
        if (tid < o) { rs[tid] += rs[tid + o]; rss[tid] += rss[tid + o]; }
        __syncthreads();
    }
    if (tid == 0) {
        float mu  = rs[0] / GSZ;
        float var = rss[0] / GSZ - mu * mu;
        stats[bg * 2]     = mu;
        stats[bg * 2 + 1] = rsqrtf(var + 1e-5f);
    }
}

// ---------------------------------------------------------------------------
// GroupNorm phase 2: normalize + split + transpose -> ht[b][p][c]
// ---------------------------------------------------------------------------
__global__ __launch_bounds__(256) void gn_apply_kernel(
    const float* __restrict__ x, const float* __restrict__ gamma,
    const float* __restrict__ beta, const float* __restrict__ stats,
    __nv_bfloat16* __restrict__ hth, __nv_bfloat16* __restrict__ htl)
{
    __shared__ float s[32][33];
    const int p0 = blockIdx.x * 32, c0 = blockIdx.y * 32, b = blockIdx.z;
    const int tid = threadIdx.x;

    #pragma unroll
    for (int q = 0; q < 4; q++) {
        int ci = (tid >> 5) + q * 8, pj = tid & 31;
        int c = c0 + ci;
        float xv = x[((size_t)b * CH + c) * NPIX + p0 + pj];
        int g = c >> 4;
        float mu = stats[(b * NGRP + g) * 2], rinv = stats[(b * NGRP + g) * 2 + 1];
        s[ci][pj] = (xv - mu) * rinv * gamma[c] + beta[c];
    }
    __syncthreads();
    #pragma unroll
    for (int q = 0; q < 4; q++) {
        int cj = tid & 31, pi = (tid >> 5) + q * 8;
        __nv_bfloat16 h, l;
        split_bf16(s[cj][pi], h, l);
        size_t o = (size_t)b * NPIX * CH + (size_t)(p0 + pi) * CH + c0 + cj;
        hth[o] = h; htl[o] = l;
    }
}

// ---------------------------------------------------------------------------
// Row softmax -> split-bf16 P (warp-shuffle reductions, fast exp)
// ---------------------------------------------------------------------------
__global__ __launch_bounds__(256) void softmax_kernel(
    const float* __restrict__ attn,
    __nv_bfloat16* __restrict__ ph, __nv_bfloat16* __restrict__ pl)
{
    const size_t row = blockIdx.x;
    const float4* p = (const float4*)(attn + row * NPIX);
    const int tid = threadIdx.x;
    const int lane = tid & 31, wrp = tid >> 5;
    __shared__ float red[8];

    float4 v = p[tid];
    float m = fmaxf(fmaxf(v.x, v.y), fmaxf(v.z, v.w));
    #pragma unroll
    for (int o = 16; o > 0; o >>= 1) m = fmaxf(m, __shfl_xor_sync(~0u, m, o));
    if (lane == 0) red[wrp] = m;
    __syncthreads();
    float rmax = red[0];
    #pragma unroll
    for (int w = 1; w < 8; w++) rmax = fmaxf(rmax, red[w]);
    __syncthreads();

    v.x = __expf(v.x - rmax); v.y = __expf(v.y - rmax);
    v.z = __expf(v.z - rmax); v.w = __expf(v.w - rmax);
    float s = v.x + v.y + v.z + v.w;
    #pragma unroll
    for (int o = 16; o > 0; o >>= 1) s += __shfl_xor_sync(~0u, s, o);
    if (lane == 0) red[wrp] = s;
    __syncthreads();
    float tot = red[0];
    #pragma unroll
    for (int w = 1; w < 8; w++) tot += red[w];

    const float rinv = 1.f / tot;
    float vals[4] = {v.x * rinv, v.y * rinv, v.z * rinv, v.w * rinv};
    __nv_bfloat16 hh[4], ll[4];
    #pragma unroll
    for (int i = 0; i < 4; i++) split_bf16(vals[i], hh[i], ll[i]);
    size_t o = row * NPIX + tid * 4;
    *(__nv_bfloat162*)(ph + o)     = __nv_bfloat162(hh[0], hh[1]);
    *(__nv_bfloat162*)(ph + o + 2) = __nv_bfloat162(hh[2], hh[3]);
    *(__nv_bfloat162*)(pl + o)     = __nv_bfloat162(ll[0], ll[1]);
    *(__nv_bfloat162*)(pl + o + 2) = __nv_bfloat162(ll[2], ll[3]);
}

// ---------------------------------------------------------------------------
// fp32 -> split-bf16 (weights)
// ---------------------------------------------------------------------------
__global__ __launch_bounds__(256) void pack_kernel(
    const float* __restrict__ w,
    __nv_bfloat16* __restrict__ oh, __nv_bfloat16* __restrict__ ol, int n)
{
    int i = (blockIdx.x * 256 + threadIdx.x) * 2;
    if (i < n) {
        __nv_bfloat16 h0, l0, h1, l1;
        split_bf16(w[i], h0, l0);
        split_bf16(w[i + 1], h1, l1);
        *(__nv_bfloat162*)(oh + i) = __nv_bfloat162(h0, h1);
        *(__nv_bfloat162*)(ol + i) = __nv_bfloat162(l0, l1);
    }
}

// ---------------------------------------------------------------------------
// Split-bf16 HMMA GEMM: D[m][n] = sum_k A[m][k]*B[n][k]  (both k-major)
// CTA 128x128, BK=32, 8 warps (2M x 4N), warp tile 64x32, 3-stage cp.async,
// one __syncthreads per k-iter.
// smem row = 128B: [hi 32 bf16 | lo 32 bf16], 16B units XOR-swizzled by row&7.
// EPI 0: QKV  1: scores  2: PV  3: proj(+bias+residual)
// ---------------------------------------------------------------------------
template<int EPI>
__global__ __launch_bounds__(256, 1) void tc_gemm(
    const __nv_bfloat16* __restrict__ Agh, const __nv_bfloat16* __restrict__ Agl,
    const __nv_bfloat16* __restrict__ Bgh, const __nv_bfloat16* __restrict__ Bgl,
    long long sAb, long long sBb, int ldA, int ldB, int K,
    const float* __restrict__ bias, float scale,
    float* __restrict__ outf,
    __nv_bfloat16* __restrict__ o0h, __nv_bfloat16* __restrict__ o0l,
    __nv_bfloat16* __restrict__ o1h, __nv_bfloat16* __restrict__ o1l,
    __nv_bfloat16* __restrict__ o2h, __nv_bfloat16* __restrict__ o2l,
    const float* __restrict__ resid)
{
    extern __shared__ char smem[];
    const uint32_t sb = smem_u32(smem);
    const int tid = threadIdx.x;
    const int lane = tid & 31, wid = tid >> 5;
    const int bz = blockIdx.z;
    const int m0 = blockIdx.y * TM;
    const int n0 = blockIdx.x * TN;

    const __nv_bfloat16* Ah = Agh + (size_t)bz * sAb + (size_t)m0 * ldA;
    const __nv_bfloat16* Al = Agl + (size_t)bz * sAb + (size_t)m0 * ldA;
    const __nv_bfloat16* Bh = Bgh + (size_t)bz * sBb + (size_t)n0 * ldB;
    const __nv_bfloat16* Bl = Bgl + (size_t)bz * sBb + (size_t)n0 * ldB;

    // loader mapping: row = tid>>1 (0..127), units (tid&1)*2 + {0,1}
    const int lrow = tid >> 1;
    const int lu0  = (tid & 1) * 2;
    const int lswz = lrow & 7;

    auto load_tile = [&](int buf, int k0) {
        const uint32_t sa  = sb + buf * STAGE_BYTES;
        const uint32_t sbB = sa + 16384;
        #pragma unroll
        for (int j = 0; j < 2; j++) {
            const int u = lu0 + j;
            const int gk = k0 + u * 8;
            CP16(sa  + lrow * 128 + ((u       ^ lswz) << 4), Ah + (size_t)lrow * ldA + gk);
            CP16(sa  + lrow * 128 + (((u + 4) ^ lswz) << 4), Al + (size_t)lrow * ldA + gk);
            CP16(sbB + lrow * 128 + ((u       ^ lswz) << 4), Bh + (size_t)lrow * ldB + gk);
            CP16(sbB + lrow * 128 + (((u + 4) ^ lswz) << 4), Bl + (size_t)lrow * ldB + gk);
        }
    };

    // warp layout: 2 (M) x 4 (N), warp tile 64x32
    const int wm = wid >> 2, wn = wid & 3;
    const int m_base = wm * 64, n_base = wn * 32;

    // ldmatrix lane mapping
    const int amat = lane >> 3;
    const int arow = (amat & 1) * 8 + (lane & 7);
    const int auadd = amat >> 1;
    const int bmat = lane >> 3;
    const int bnrow = (bmat >> 1) * 8 + (lane & 7);
    const int buadd = bmat & 1;

    float acc[4][4][4] = {};

    load_tile(0, 0);
    CP_COMMIT();
    load_tile(1, TK);
    CP_COMMIT();

    const int nk = K / TK;
    for (int i = 0; i < nk; i++) {
        if (i == nk - 1) { CP_WAIT0(); } else { CP_WAIT1(); }
        __syncthreads();
        if (i + 2 < nk) {
            load_tile((i + 2) % NSTAGE, (i + 2) * TK);
            CP_COMMIT();
        }
        const uint32_t sa  = sb + (i % NSTAGE) * STAGE_BYTES;
        const uint32_t sbB = sa + 16384;

        #pragma unroll
        for (int kk = 0; kk < 2; kk++) {
            uint32_t ah[4][4], al[4][4], bh[8], bl[8];
            #pragma unroll
            for (int mt = 0; mt < 4; mt++) {
                const int row = m_base + mt * 16 + arow;
                const int rx = row & 7;
                const uint32_t base = sa + row * 128;
                const int uh = kk * 2 + auadd;
                LDSM4(ah[mt][0], ah[mt][1], ah[mt][2], ah[mt][3], base + ((uh ^ rx) << 4));
                LDSM4(al[mt][0], al[mt][1], al[mt][2], al[mt][3], base + (((uh + 4) ^ rx) << 4));
            }
            #pragma unroll
            for (int np = 0; np < 2; np++) {
                const int n = n_base + np * 16 + bnrow;
                const int rx = n & 7;
                const uint32_t base = sbB + n * 128;
                const int uh = kk * 2 + buadd;
                LDSM4(bh[np * 4 + 0], bh[np * 4 + 1], bh[np * 4 + 2], bh[np * 4 + 3],
                      base + ((uh ^ rx) << 4));
                LDSM4(bl[np * 4 + 0], bl[np * 4 + 1], bl[np * 4 + 2], bl[np * 4 + 3],
                      base + (((uh + 4) ^ rx) << 4));
            }
            #pragma unroll
            for (int mt = 0; mt < 4; mt++) {
                #pragma unroll
                for (int nt = 0; nt < 4; nt++) {
                    const int r = (nt >> 1) * 4 + (nt & 1) * 2;
                    MMA_BF16(acc[mt][nt], ah[mt], bh[r], bh[r + 1]);
                    MMA_BF16(acc[mt][nt], ah[mt], bl[r], bl[r + 1]);
                    MMA_BF16(acc[mt][nt], al[mt], bh[r], bh[r + 1]);
                }
            }
        }
    }

    // ---- stage accumulators to smem fp32 (reuse pipeline smem) ----
    __syncthreads();
    float* s = (float*)smem;
    #pragma unroll
    for (int mt = 0; mt < 4; mt++)
        #pragma unroll
        for (int nt = 0; nt < 4; nt++)
            #pragma unroll
            for (int r = 0; r < 4; r++) {
                const int row = m_base + mt * 16 + (lane >> 2) + (r >= 2 ? 8 : 0);
                const int col = n_base + nt * 8 + (lane & 3) * 2 + (r & 1);
                s[row * SPITCH + col] = acc[mt][nt][r];
            }
    __syncthreads();

    // ---- writers ----
    if (EPI == 0 && m0 < 2 * CH) {
        // Q or K tile: [p][c] output, m-fast pairs for coalescing over c
        __nv_bfloat16* dh = (m0 < CH ? o0h : o1h) + (size_t)bz * NPIX * CH;
        __nv_bfloat16* dl = (m0 < CH ? o0l : o1l) + (size_t)bz * NPIX * CH;
        const int coff = m0 & (CH - 1);
        for (int it = 0; it < 32; it++) {
            const int idx = it * 512 + tid * 2;
            const int n = idx >> 7, m = idx & 127;
            float v0 = s[m * SPITCH + n] + bias[m0 + m];
            float v1 = s[(m + 1) * SPITCH + n] + bias[m0 + m + 1];
            __nv_bfloat16 h0, l0, h1, l1;
            split_bf16(v0, h0, l0); split_bf16(v1, h1, l1);
            const size_t o = (size_t)(n0 + n) * CH + coff + m;
            *(__nv_bfloat162*)(dh + o) = __nv_bfloat162(h0, h1);
            *(__nv_bfloat162*)(dl + o) = __nv_bfloat162(l0, l1);
        }
    } else {
        for (int it = 0; it < 32; it++) {
            const int idx = it * 512 + tid * 2;
            const int m = idx >> 7, n = idx & 127;
            float v0 = s[m * SPITCH + n];
            float v1 = s[m * SPITCH + n + 1];
            if (EPI == 0) {          // V tile -> v[b][c][p]
                const int c = m0 - 2 * CH + m;
                v0 += bias[m0 + m]; v1 += bias[m0 + m];
                __nv_bfloat16 h0, l0, h1, l1;
                split_bf16(v0, h0, l0); split_bf16(v1, h1, l1);
                const size_t o = ((size_t)bz * CH + c) * NPIX + n0 + n;
                *(__nv_bfloat162*)(o2h + o) = __nv_bfloat162(h0, h1);
                *(__nv_bfloat162*)(o2l + o) = __nv_bfloat162(l0, l1);
            } else if (EPI == 1) {   // scores fp32
                const size_t o = ((size_t)bz * NPIX + m0 + m) * NPIX + n0 + n;
                *(float2*)(outf + o) = make_float2(v0 * scale, v1 * scale);
            } else if (EPI == 2) {   // Ot split [p][c]
                __nv_bfloat16 h0, l0, h1, l1;
                split_bf16(v0, h0, l0); split_bf16(v1, h1, l1);
                const size_t o = ((size_t)bz * NPIX + m0 + m) * CH + n0 + n;
                *(__nv_bfloat162*)(o0h + o) = __nv_bfloat162(h0, h1);
                *(__nv_bfloat162*)(o0l + o) = __nv_bfloat162(l0, l1);
            } else {                 // proj + bias + residual
                const float bv = bias[m0 + m];
                const size_t o = ((size_t)bz * CH + m0 + m) * NPIX + n0 + n;
                float2 rv = *(const float2*)(resid + o);
                *(float2*)(outf + o) = make_float2(v0 + bv + rv.x, v1 + bv + rv.y);
            }
        }
    }
}

// ---------------------------------------------------------------------------
extern "C" void kernel_launch(void* const* d_in, const int* in_sizes, int n_in,
                              void* d_out, int out_size)
{
    const float* x      = (const float*)d_in[0];
    const float* gamma  = (const float*)d_in[1];
    const float* beta   = (const float*)d_in[2];
    const float* w_qkv  = (const float*)d_in[3];
    const float* b_qkv  = (const float*)d_in[4];
    const float* w_proj = (const float*)d_in[5];
    const float* b_proj = (const float*)d_in[6];
    float* out = (float*)d_out;

    __nv_bfloat16 *hth, *htl, *qh, *ql, *kh, *kl, *vh, *vl, *ph, *pl,
                  *oth, *otl, *wqh, *wql, *wph, *wpl;
    float *attn, *stats;
    cudaGetSymbolAddress((void**)&hth, g_ht_h); cudaGetSymbolAddress((void**)&htl, g_ht_l);
    cudaGetSymbolAddress((void**)&qh,  g_q_h ); cudaGetSymbolAddress((void**)&ql,  g_q_l );
    cudaGetSymbolAddress((void**)&kh,  g_k_h ); cudaGetSymbolAddress((void**)&kl,  g_k_l );
    cudaGetSymbolAddress((void**)&vh,  g_v_h ); cudaGetSymbolAddress((void**)&vl,  g_v_l );
    cudaGetSymbolAddress((void**)&ph,  g_p_h ); cudaGetSymbolAddress((void**)&pl,  g_p_l );
    cudaGetSymbolAddress((void**)&oth, g_ot_h); cudaGetSymbolAddress((void**)&otl, g_ot_l);
    cudaGetSymbolAddress((void**)&wqh, g_wq_h); cudaGetSymbolAddress((void**)&wql, g_wq_l);
    cudaGetSymbolAddress((void**)&wph, g_wp_h); cudaGetSymbolAddress((void**)&wpl, g_wp_l);
    cudaGetSymbolAddress((void**)&attn, g_attn);
    cudaGetSymbolAddress((void**)&stats, g_stats);

    cudaFuncSetAttribute(tc_gemm<0>, cudaFuncAttributeMaxDynamicSharedMemorySize, SMEM_BYTES);
    cudaFuncSetAttribute(tc_gemm<1>, cudaFuncAttributeMaxDynamicSharedMemorySize, SMEM_BYTES);
    cudaFuncSetAttribute(tc_gemm<2>, cudaFuncAttributeMaxDynamicSharedMemorySize, SMEM_BYTES);
    cudaFuncSetAttribute(tc_gemm<3>, cudaFuncAttributeMaxDynamicSharedMemorySize, SMEM_BYTES);

    const long long sH = (long long)NPIX * CH;
    const long long sP = (long long)NPIX * NPIX;

    pack_kernel<<<(3 * CH * CH / 2 + 255) / 256, 256>>>(w_qkv, wqh, wql, 3 * CH * CH);
    pack_kernel<<<(CH * CH / 2 + 255) / 256, 256>>>(w_proj, wph, wpl, CH * CH);
    gn_stats_kernel<<<NB * NGRP, 256>>>(x, stats);
    gn_apply_kernel<<<dim3(NPIX / 32, CH / 32, NB), 256>>>(x, gamma, beta, stats, hth, htl);

    // QKV: A = w_qkv [1536,512], B = ht[b][p][c] -> q/k [p][c], v [c][p]
    tc_gemm<0><<<dim3(NPIX / TN, 1536 / TM, NB), 256, SMEM_BYTES>>>(
        wqh, wql, hth, htl, 0, sH, CH, CH, CH,
        b_qkv, 1.f, nullptr, qh, ql, kh, kl, vh, vl, nullptr);

    // scores: q[i][c] . k[j][c] * scale -> attn fp32
    tc_gemm<1><<<dim3(NPIX / TN, NPIX / TM, NB), 256, SMEM_BYTES>>>(
        qh, ql, kh, kl, sH, sH, CH, CH, CH,
        nullptr, 1.0f / sqrtf((float)CH), attn,
        nullptr, nullptr, nullptr, nullptr, nullptr, nullptr, nullptr);

    softmax_kernel<<<NB * NPIX, 256>>>(attn, ph, pl);

    // PV: p[i][j] . v[c][j] -> ot[p][c]
    tc_gemm<2><<<dim3(CH / TN, NPIX / TM, NB), 256, SMEM_BYTES>>>(
        ph, pl, vh, vl, sP, sH, NPIX, NPIX, NPIX,
        nullptr, 1.f, nullptr, oth, otl,
        nullptr, nullptr, nullptr, nullptr, nullptr);

    // proj: w_proj[o][c] . ot[p][c] + bias + residual -> out [b][c][p]
    tc_gemm<3><<<dim3(NPIX / TN, CH / TM, NB), 256, SMEM_BYTES>>>(
        wph, wpl, oth, otl, 0, sH, CH, CH, CH,
        b_proj, 1.f, out, nullptr, nullptr, nullptr, nullptr, nullptr, nullptr, x);
}

// round 6
// speedup vs baseline: 1.2094x; 1.0010x over previous
#include <cuda_runtime.h>
#include <cuda_bf16.h>
#include <math.h>
#include <stdint.h>

// ---------------------------------------------------------------------------
// Problem constants
// ---------------------------------------------------------------------------
constexpr int NB   = 16;
constexpr int CH   = 512;
constexpr int NPIX = 1024;
constexpr int NGRP = 32;

// GEMM tiling: CTA 128x128, BK=32, 8 warps (2M x 4N), warp tile 64x32
constexpr int TM = 128, TN = 128, TK = 32;

constexpr int STAGE_BYTES = 32768;                  // A 16KB + B 16KB
constexpr int NSTAGE      = 3;
constexpr int SPITCH      = 129;                    // fp32 epilogue pitch
constexpr int SMEM_BYTES  = NSTAGE * STAGE_BYTES;   // 98304 (>= 128*129*4)

// ---------------------------------------------------------------------------
// Scratch (__device__ globals; allocation-free rule). hi/lo split-bf16 pairs.
// ---------------------------------------------------------------------------
#define BALIGN __align__(256)
__device__ BALIGN __nv_bfloat16 g_ht_h[(size_t)NB * NPIX * CH];
__device__ BALIGN __nv_bfloat16 g_ht_l[(size_t)NB * NPIX * CH];
__device__ BALIGN __nv_bfloat16 g_q_h [(size_t)NB * NPIX * CH];
__device__ BALIGN __nv_bfloat16 g_q_l [(size_t)NB * NPIX * CH];
__device__ BALIGN __nv_bfloat16 g_k_h [(size_t)NB * NPIX * CH];
__device__ BALIGN __nv_bfloat16 g_k_l [(size_t)NB * NPIX * CH];
__device__ BALIGN __nv_bfloat16 g_v_h [(size_t)NB * CH * NPIX];
__device__ BALIGN __nv_bfloat16 g_v_l [(size_t)NB * CH * NPIX];
__device__ BALIGN __nv_bfloat16 g_p_h [(size_t)NB * NPIX * NPIX];
__device__ BALIGN __nv_bfloat16 g_p_l [(size_t)NB * NPIX * NPIX];
__device__ BALIGN __nv_bfloat16 g_ot_h[(size_t)NB * NPIX * CH];
__device__ BALIGN __nv_bfloat16 g_ot_l[(size_t)NB * NPIX * CH];
__device__ BALIGN __nv_bfloat16 g_wq_h[(size_t)3 * CH * CH];
__device__ BALIGN __nv_bfloat16 g_wq_l[(size_t)3 * CH * CH];
__device__ BALIGN __nv_bfloat16 g_wp_h[(size_t)CH * CH];
__device__ BALIGN __nv_bfloat16 g_wp_l[(size_t)CH * CH];
__device__ BALIGN float         g_attn[(size_t)NB * NPIX * NPIX];
__device__ float g_stats[NB * NGRP * 2];

// ---------------------------------------------------------------------------
// helpers
// ---------------------------------------------------------------------------
__device__ __forceinline__ uint32_t smem_u32(const void* p) {
    uint32_t a;
    asm("{ .reg .u64 t; cvta.to.shared.u64 t, %1; cvt.u32.u64 %0, t; }" : "=r"(a) : "l"(p));
    return a;
}
__device__ __forceinline__ void split_bf16(float v, __nv_bfloat16& h, __nv_bfloat16& l) {
    h = __float2bfloat16(v);
    l = __float2bfloat16(v - __bfloat162float(h));
}

#define CP16(sm, gp) asm volatile("cp.async.cg.shared.global [%0], [%1], 16;" :: "r"(sm), "l"(gp))
#define CP_COMMIT()  asm volatile("cp.async.commit_group;" ::: "memory")
#define CP_WAIT0()   asm volatile("cp.async.wait_group 0;" ::: "memory")
#define CP_WAIT1()   asm volatile("cp.async.wait_group 1;" ::: "memory")

#define LDSM4(r0, r1, r2, r3, a) \
    asm volatile("ldmatrix.sync.aligned.m8n8.x4.shared.b16 {%0,%1,%2,%3}, [%4];" \
                 : "=r"(r0), "=r"(r1), "=r"(r2), "=r"(r3) : "r"(a))

#define MMA_BF16(d, a, b0, b1) \
    asm volatile("mma.sync.aligned.m16n8k16.row.col.f32.bf16.bf16.f32 " \
                 "{%0,%1,%2,%3},{%4,%5,%6,%7},{%8,%9},{%0,%1,%2,%3};" \
                 : "+f"((d)[0]), "+f"((d)[1]), "+f"((d)[2]), "+f"((d)[3]) \
                 : "r"((a)[0]), "r"((a)[1]), "r"((a)[2]), "r"((a)[3]), "r"(b0), "r"(b1))

// ---------------------------------------------------------------------------
// GroupNorm phase 1: per-(b,g) mean / rstd
// ---------------------------------------------------------------------------
__global__ __launch_bounds__(256) void gn_stats_kernel(
    const float* __restrict__ x, float* __restrict__ stats)
{
    const int GSZ = (CH / NGRP) * NPIX;
    const int bg  = blockIdx.x;
    const float4* xv = (const float4*)(x + (size_t)bg * GSZ);
    const int tid = threadIdx.x;

    float s = 0.f, ss = 0.f;
    for (int i = tid; i < GSZ / 4; i += 256) {
        float4 v = xv[i];
        s  += v.x + v.y + v.z + v.w;
        ss += v.x * v.x + v.y * v.y + v.z * v.z + v.w * v.w;
    }
    __shared__ float rs[256], rss[256];
    rs[tid] = s; rss[tid] = ss;
    __syncthreads();
    for (int o = 128; o > 0; o >>= 1) {
        if (tid < o) { rs[tid] += rs[tid + o]; rss[tid] += rss[tid + o]; }
        __syncthreads();
    }
    if (tid == 0) {
        float mu  = rs[0] / GSZ;
        float var = rss[0] / GSZ - mu * mu;
        stats[bg * 2]     = mu;
        stats[bg * 2 + 1] = rsqrtf(var + 1e-5f);
    }
}

// ---------------------------------------------------------------------------
// GroupNorm phase 2: normalize + split + transpose -> ht[b][p][c]
// ---------------------------------------------------------------------------
__global__ __launch_bounds__(256) void gn_apply_kernel(
    const float* __restrict__ x, const float* __restrict__ gamma,
    const float* __restrict__ beta, const float* __restrict__ stats,
    __nv_bfloat16* __restrict__ hth, __nv_bfloat16* __restrict__ htl)
{
    __shared__ float s[32][33];
    const int p0 = blockIdx.x * 32, c0 = blockIdx.y * 32, b = blockIdx.z;
    const int tid = threadIdx.x;

    #pragma unroll
    for (int q = 0; q < 4; q++) {
        int ci = (tid >> 5) + q * 8, pj = tid & 31;
        int c = c0 + ci;
        float xv = x[((size_t)b * CH + c) * NPIX + p0 + pj];
        int g = c >> 4;
        float mu = stats[(b * NGRP + g) * 2], rinv = stats[(b * NGRP + g) * 2 + 1];
        s[ci][pj] = (xv - mu) * rinv * gamma[c] + beta[c];
    }
    __syncthreads();
    #pragma unroll
    for (int q = 0; q < 4; q++) {
        int cj = tid & 31, pi = (tid >> 5) + q * 8;
        __nv_bfloat16 h, l;
        split_bf16(s[cj][pi], h, l);
        size_t o = (size_t)b * NPIX * CH + (size_t)(p0 + pi) * CH + c0 + cj;
        hth[o] = h; htl[o] = l;
    }
}

// ---------------------------------------------------------------------------
// Row softmax -> split-bf16 P (warp-shuffle reductions, fast exp)
// ---------------------------------------------------------------------------
__global__ __launch_bounds__(256) void softmax_kernel(
    const float* __restrict__ attn,
    __nv_bfloat16* __restrict__ ph, __nv_bfloat16* __restrict__ pl)
{
    const size_t row = blockIdx.x;
    const float4* p = (const float4*)(attn + row * NPIX);
    const int tid = threadIdx.x;
    const int lane = tid & 31, wrp = tid >> 5;
    __shared__ float red[8];

    float4 v = p[tid];
    float m = fmaxf(fmaxf(v.x, v.y), fmaxf(v.z, v.w));
    #pragma unroll
    for (int o = 16; o > 0; o >>= 1) m = fmaxf(m, __shfl_xor_sync(~0u, m, o));
    if (lane == 0) red[wrp] = m;
    __syncthreads();
    float rmax = red[0];
    #pragma unroll
    for (int w = 1; w < 8; w++) rmax = fmaxf(rmax, red[w]);
    __syncthreads();

    v.x = __expf(v.x - rmax); v.y = __expf(v.y - rmax);
    v.z = __expf(v.z - rmax); v.w = __expf(v.w - rmax);
    float s = v.x + v.y + v.z + v.w;
    #pragma unroll
    for (int o = 16; o > 0; o >>= 1) s += __shfl_xor_sync(~0u, s, o);
    if (lane == 0) red[wrp] = s;
    __syncthreads();
    float tot = red[0];
    #pragma unroll
    for (int w = 1; w < 8; w++) tot += red[w];

    const float rinv = 1.f / tot;
    float vals[4] = {v.x * rinv, v.y * rinv, v.z * rinv, v.w * rinv};
    __nv_bfloat16 hh[4], ll[4];
    #pragma unroll
    for (int i = 0; i < 4; i++) split_bf16(vals[i], hh[i], ll[i]);
    size_t o = row * NPIX + tid * 4;
    *(__nv_bfloat162*)(ph + o)     = __nv_bfloat162(hh[0], hh[1]);
    *(__nv_bfloat162*)(ph + o + 2) = __nv_bfloat162(hh[2], hh[3]);
    *(__nv_bfloat162*)(pl + o)     = __nv_bfloat162(ll[0], ll[1]);
    *(__nv_bfloat162*)(pl + o + 2) = __nv_bfloat162(ll[2], ll[3]);
}

// ---------------------------------------------------------------------------
// fp32 -> split-bf16 (weights)
// ---------------------------------------------------------------------------
__global__ __launch_bounds__(256) void pack_kernel(
    const float* __restrict__ w,
    __nv_bfloat16* __restrict__ oh, __nv_bfloat16* __restrict__ ol, int n)
{
    int i = (blockIdx.x * 256 + threadIdx.x) * 2;
    if (i < n) {
        __nv_bfloat16 h0, l0, h1, l1;
        split_bf16(w[i], h0, l0);
        split_bf16(w[i + 1], h1, l1);
        *(__nv_bfloat162*)(oh + i) = __nv_bfloat162(h0, h1);
        *(__nv_bfloat162*)(ol + i) = __nv_bfloat162(l0, l1);
    }
}

// ---------------------------------------------------------------------------
// Split-bf16 HMMA GEMM: D[m][n] = sum_k A[m][k]*B[n][k]  (both k-major)
// CTA 128x128, BK=32, 8 warps (2M x 4N), warp tile 64x32, 3-stage cp.async,
// one __syncthreads per k-iter.
// smem row = 128B: [hi 32 bf16 | lo 32 bf16], 16B units XOR-swizzled by row&7.
// EPI 0: QKV  1: scores  2: PV  3: proj(+bias+residual)
// ---------------------------------------------------------------------------
template<int EPI>
__global__ __launch_bounds__(256, 1) void tc_gemm(
    const __nv_bfloat16* __restrict__ Agh, const __nv_bfloat16* __restrict__ Agl,
    const __nv_bfloat16* __restrict__ Bgh, const __nv_bfloat16* __restrict__ Bgl,
    long long sAb, long long sBb, int ldA, int ldB, int K,
    const float* __restrict__ bias, float scale,
    float* __restrict__ outf,
    __nv_bfloat16* __restrict__ o0h, __nv_bfloat16* __restrict__ o0l,
    __nv_bfloat16* __restrict__ o1h, __nv_bfloat16* __restrict__ o1l,
    __nv_bfloat16* __restrict__ o2h, __nv_bfloat16* __restrict__ o2l,
    const float* __restrict__ resid)
{
    extern __shared__ char smem[];
    const uint32_t sb = smem_u32(smem);
    const int tid = threadIdx.x;
    const int lane = tid & 31, wid = tid >> 5;
    const int bz = blockIdx.z;
    const int m0 = blockIdx.y * TM;
    const int n0 = blockIdx.x * TN;

    const __nv_bfloat16* Ah = Agh + (size_t)bz * sAb + (size_t)m0 * ldA;
    const __nv_bfloat16* Al = Agl + (size_t)bz * sAb + (size_t)m0 * ldA;
    const __nv_bfloat16* Bh = Bgh + (size_t)bz * sBb + (size_t)n0 * ldB;
    const __nv_bfloat16* Bl = Bgl + (size_t)bz * sBb + (size_t)n0 * ldB;

    // loader mapping: row = tid>>1 (0..127), units (tid&1)*2 + {0,1}
    const int lrow = tid >> 1;
    const int lu0  = (tid & 1) * 2;
    const int lswz = lrow & 7;

    auto load_tile = [&](int buf, int k0) {
        const uint32_t sa  = sb + buf * STAGE_BYTES;
        const uint32_t sbB = sa + 16384;
        #pragma unroll
        for (int j = 0; j < 2; j++) {
            const int u = lu0 + j;
            const int gk = k0 + u * 8;
            CP16(sa  + lrow * 128 + ((u       ^ lswz) << 4), Ah + (size_t)lrow * ldA + gk);
            CP16(sa  + lrow * 128 + (((u + 4) ^ lswz) << 4), Al + (size_t)lrow * ldA + gk);
            CP16(sbB + lrow * 128 + ((u       ^ lswz) << 4), Bh + (size_t)lrow * ldB + gk);
            CP16(sbB + lrow * 128 + (((u + 4) ^ lswz) << 4), Bl + (size_t)lrow * ldB + gk);
        }
    };

    // warp layout: 2 (M) x 4 (N), warp tile 64x32
    const int wm = wid >> 2, wn = wid & 3;
    const int m_base = wm * 64, n_base = wn * 32;

    // ldmatrix lane mapping
    const int amat = lane >> 3;
    const int arow = (amat & 1) * 8 + (lane & 7);
    const int auadd = amat >> 1;
    const int bmat = lane >> 3;
    const int bnrow = (bmat >> 1) * 8 + (lane & 7);
    const int buadd = bmat & 1;

    float acc[4][4][4] = {};

    load_tile(0, 0);
    CP_COMMIT();
    load_tile(1, TK);
    CP_COMMIT();

    const int nk = K / TK;
    for (int i = 0; i < nk; i++) {
        if (i == nk - 1) { CP_WAIT0(); } else { CP_WAIT1(); }
        __syncthreads();
        if (i + 2 < nk) {
            load_tile((i + 2) % NSTAGE, (i + 2) * TK);
            CP_COMMIT();
        }
        const uint32_t sa  = sb + (i % NSTAGE) * STAGE_BYTES;
        const uint32_t sbB = sa + 16384;

        #pragma unroll
        for (int kk = 0; kk < 2; kk++) {
            uint32_t ah[4][4], al[4][4], bh[8], bl[8];
            #pragma unroll
            for (int mt = 0; mt < 4; mt++) {
                const int row = m_base + mt * 16 + arow;
                const int rx = row & 7;
                const uint32_t base = sa + row * 128;
                const int uh = kk * 2 + auadd;
                LDSM4(ah[mt][0], ah[mt][1], ah[mt][2], ah[mt][3], base + ((uh ^ rx) << 4));
                LDSM4(al[mt][0], al[mt][1], al[mt][2], al[mt][3], base + (((uh + 4) ^ rx) << 4));
            }
            #pragma unroll
            for (int np = 0; np < 2; np++) {
                const int n = n_base + np * 16 + bnrow;
                const int rx = n & 7;
                const uint32_t base = sbB + n * 128;
                const int uh = kk * 2 + buadd;
                LDSM4(bh[np * 4 + 0], bh[np * 4 + 1], bh[np * 4 + 2], bh[np * 4 + 3],
                      base + ((uh ^ rx) << 4));
                LDSM4(bl[np * 4 + 0], bl[np * 4 + 1], bl[np * 4 + 2], bl[np * 4 + 3],
                      base + (((uh + 4) ^ rx) << 4));
            }
            #pragma unroll
            for (int mt = 0; mt < 4; mt++) {
                #pragma unroll
                for (int nt = 0; nt < 4; nt++) {
                    const int r = (nt >> 1) * 4 + (nt & 1) * 2;
                    MMA_BF16(acc[mt][nt], ah[mt], bh[r], bh[r + 1]);
                    MMA_BF16(acc[mt][nt], ah[mt], bl[r], bl[r + 1]);
                    MMA_BF16(acc[mt][nt], al[mt], bh[r], bh[r + 1]);
                }
            }
        }
    }

    // ---- stage accumulators to smem fp32 (reuse pipeline smem) ----
    __syncthreads();
    float* s = (float*)smem;
    #pragma unroll
    for (int mt = 0; mt < 4; mt++)
        #pragma unroll
        for (int nt = 0; nt < 4; nt++)
            #pragma unroll
            for (int r = 0; r < 4; r++) {
                const int row = m_base + mt * 16 + (lane >> 2) + (r >= 2 ? 8 : 0);
                const int col = n_base + nt * 8 + (lane & 3) * 2 + (r & 1);
                s[row * SPITCH + col] = acc[mt][nt][r];
            }
    __syncthreads();

    // ---- writers ----
    if (EPI == 0 && m0 < 2 * CH) {
        // Q or K tile: [p][c] output, m-fast pairs for coalescing over c
        __nv_bfloat16* dh = (m0 < CH ? o0h : o1h) + (size_t)bz * NPIX * CH;
        __nv_bfloat16* dl = (m0 < CH ? o0l : o1l) + (size_t)bz * NPIX * CH;
        const int coff = m0 & (CH - 1);
        for (int it = 0; it < 32; it++) {
            const int idx = it * 512 + tid * 2;
            const int n = idx >> 7, m = idx & 127;
            float v0 = s[m * SPITCH + n] + bias[m0 + m];
            float v1 = s[(m + 1) * SPITCH + n] + bias[m0 + m + 1];
            __nv_bfloat16 h0, l0, h1, l1;
            split_bf16(v0, h0, l0); split_bf16(v1, h1, l1);
            const size_t o = (size_t)(n0 + n) * CH + coff + m;
            *(__nv_bfloat162*)(dh + o) = __nv_bfloat162(h0, h1);
            *(__nv_bfloat162*)(dl + o) = __nv_bfloat162(l0, l1);
        }
    } else {
        for (int it = 0; it < 32; it++) {
            const int idx = it * 512 + tid * 2;
            const int m = idx >> 7, n = idx & 127;
            float v0 = s[m * SPITCH + n];
            float v1 = s[m * SPITCH + n + 1];
            if (EPI == 0) {          // V tile -> v[b][c][p]
                const int c = m0 - 2 * CH + m;
                v0 += bias[m0 + m]; v1 += bias[m0 + m];
                __nv_bfloat16 h0, l0, h1, l1;
                split_bf16(v0, h0, l0); split_bf16(v1, h1, l1);
                const size_t o = ((size_t)bz * CH + c) * NPIX + n0 + n;
                *(__nv_bfloat162*)(o2h + o) = __nv_bfloat162(h0, h1);
                *(__nv_bfloat162*)(o2l + o) = __nv_bfloat162(l0, l1);
            } else if (EPI == 1) {   // scores fp32
                const size_t o = ((size_t)bz * NPIX + m0 + m) * NPIX + n0 + n;
                *(float2*)(outf + o) = make_float2(v0 * scale, v1 * scale);
            } else if (EPI == 2) {   // Ot split [p][c]
                __nv_bfloat16 h0, l0, h1, l1;
                split_bf16(v0, h0, l0); split_bf16(v1, h1, l1);
                const size_t o = ((size_t)bz * NPIX + m0 + m) * CH + n0 + n;
                *(__nv_bfloat162*)(o0h + o) = __nv_bfloat162(h0, h1);
                *(__nv_bfloat162*)(o0l + o) = __nv_bfloat162(l0, l1);
            } else {                 // proj + bias + residual
                const float bv = bias[m0 + m];
                const size_t o = ((size_t)bz * CH + m0 + m) * NPIX + n0 + n;
                float2 rv = *(const float2*)(resid + o);
                *(float2*)(outf + o) = make_float2(v0 + bv + rv.x, v1 + bv + rv.y);
            }
        }
    }
}

// ---------------------------------------------------------------------------
extern "C" void kernel_launch(void* const* d_in, const int* in_sizes, int n_in,
                              void* d_out, int out_size)
{
    const float* x      = (const float*)d_in[0];
    const float* gamma  = (const float*)d_in[1];
    const float* beta   = (const float*)d_in[2];
    const float* w_qkv  = (const float*)d_in[3];
    const float* b_qkv  = (const float*)d_in[4];
    const float* w_proj = (const float*)d_in[5];
    const float* b_proj = (const float*)d_in[6];
    float* out = (float*)d_out;

    __nv_bfloat16 *hth, *htl, *qh, *ql, *kh, *kl, *vh, *vl, *ph, *pl,
                  *oth, *otl, *wqh, *wql, *wph, *wpl;
    float *attn, *stats;
    cudaGetSymbolAddress((void**)&hth, g_ht_h); cudaGetSymbolAddress((void**)&htl, g_ht_l);
    cudaGetSymbolAddress((void**)&qh,  g_q_h ); cudaGetSymbolAddress((void**)&ql,  g_q_l );
    cudaGetSymbolAddress((void**)&kh,  g_k_h ); cudaGetSymbolAddress((void**)&kl,  g_k_l );
    cudaGetSymbolAddress((void**)&vh,  g_v_h ); cudaGetSymbolAddress((void**)&vl,  g_v_l );
    cudaGetSymbolAddress((void**)&ph,  g_p_h ); cudaGetSymbolAddress((void**)&pl,  g_p_l );
    cudaGetSymbolAddress((void**)&oth, g_ot_h); cudaGetSymbolAddress((void**)&otl, g_ot_l);
    cudaGetSymbolAddress((void**)&wqh, g_wq_h); cudaGetSymbolAddress((void**)&wql, g_wq_l);
    cudaGetSymbolAddress((void**)&wph, g_wp_h); cudaGetSymbolAddress((void**)&wpl, g_wp_l);
    cudaGetSymbolAddress((void**)&attn, g_attn);
    cudaGetSymbolAddress((void**)&stats, g_stats);

    cudaFuncSetAttribute(tc_gemm<0>, cudaFuncAttributeMaxDynamicSharedMemorySize, SMEM_BYTES);
    cudaFuncSetAttribute(tc_gemm<1>, cudaFuncAttributeMaxDynamicSharedMemorySize, SMEM_BYTES);
    cudaFuncSetAttribute(tc_gemm<2>, cudaFuncAttributeMaxDynamicSharedMemorySize, SMEM_BYTES);
    cudaFuncSetAttribute(tc_gemm<3>, cudaFuncAttributeMaxDynamicSharedMemorySize, SMEM_BYTES);

    const long long sH = (long long)NPIX * CH;
    const long long sP = (long long)NPIX * NPIX;

    pack_kernel<<<(3 * CH * CH / 2 + 255) / 256, 256>>>(w_qkv, wqh, wql, 3 * CH * CH);
    pack_kernel<<<(CH * CH / 2 + 255) / 256, 256>>>(w_proj, wph, wpl, CH * CH);
    gn_stats_kernel<<<NB * NGRP, 256>>>(x, stats);
    gn_apply_kernel<<<dim3(NPIX / 32, CH / 32, NB), 256>>>(x, gamma, beta, stats, hth, htl);

    // QKV: A = w_qkv [1536,512], B = ht[b][p][c] -> q/k [p][c], v [c][p]
    tc_gemm<0><<<dim3(NPIX / TN, 1536 / TM, NB), 256, SMEM_BYTES>>>(
        wqh, wql, hth, htl, 0, sH, CH, CH, CH,
        b_qkv, 1.f, nullptr, qh, ql, kh, kl, vh, vl, nullptr);

    // scores: q[i][c] . k[j][c] * scale -> attn fp32
    tc_gemm<1><<<dim3(NPIX / TN, NPIX / TM, NB), 256, SMEM_BYTES>>>(
        qh, ql, kh, kl, sH, sH, CH, CH, CH,
        nullptr, 1.0f / sqrtf((float)CH), attn,
        nullptr, nullptr, nullptr, nullptr, nullptr, nullptr, nullptr);

    softmax_kernel<<<NB * NPIX, 256>>>(attn, ph, pl);

    // PV: p[i][j] . v[c][j] -> ot[p][c]
    tc_gemm<2><<<dim3(CH / TN, NPIX / TM, NB), 256, SMEM_BYTES>>>(
        ph, pl, vh, vl, sP, sH, NPIX, NPIX, NPIX,
        nullptr, 1.f, nullptr, oth, otl,
        nullptr, nullptr, nullptr, nullptr, nullptr);

    // proj: w_proj[o][c] . ot[p][c] + bias + residual -> out [b][c][p]
    tc_gemm<3><<<dim3(NPIX / TN, CH / TM, NB), 256, SMEM_BYTES>>>(
        wph, wpl, oth, otl, 0, sH, CH, CH, CH,
        b_proj, 1.f, out, nullptr, nullptr, nullptr, nullptr, nullptr, nullptr, x);
}

// round 7
// speedup vs baseline: 1.4071x; 1.1635x over previous
#include <cuda_runtime.h>
#include <cuda_bf16.h>
#include <math.h>
#include <stdint.h>

// ---------------------------------------------------------------------------
// Problem constants
// ---------------------------------------------------------------------------
constexpr int NB   = 16;
constexpr int CH   = 512;
constexpr int NPIX = 1024;
constexpr int NGRP = 32;

// GEMM tiling: CTA 128x128, BK=32, 8 warps (2M x 4N), warp tile 64x32
constexpr int TM = 128, TN = 128, TK = 32;

constexpr int STAGE_BYTES = 32768;                  // A 16KB + B 16KB
constexpr int NSTAGE      = 3;
constexpr int SPITCH      = 129;                    // fp32 epilogue pitch
constexpr int SMEM_BYTES  = NSTAGE * STAGE_BYTES;   // 98304 (>= 128*129*4)

// ---------------------------------------------------------------------------
// Scratch (__device__ globals; allocation-free rule). hi/lo split-bf16 pairs.
// ---------------------------------------------------------------------------
#define BALIGN __align__(256)
__device__ BALIGN __nv_bfloat16 g_ht_h[(size_t)NB * NPIX * CH];
__device__ BALIGN __nv_bfloat16 g_ht_l[(size_t)NB * NPIX * CH];
__device__ BALIGN __nv_bfloat16 g_q_h [(size_t)NB * NPIX * CH];
__device__ BALIGN __nv_bfloat16 g_q_l [(size_t)NB * NPIX * CH];
__device__ BALIGN __nv_bfloat16 g_k_h [(size_t)NB * NPIX * CH];
__device__ BALIGN __nv_bfloat16 g_k_l [(size_t)NB * NPIX * CH];
__device__ BALIGN __nv_bfloat16 g_v_h [(size_t)NB * CH * NPIX];
__device__ BALIGN __nv_bfloat16 g_v_l [(size_t)NB * CH * NPIX];
__device__ BALIGN __nv_bfloat16 g_p_h [(size_t)NB * NPIX * NPIX];
__device__ BALIGN __nv_bfloat16 g_p_l [(size_t)NB * NPIX * NPIX];
__device__ BALIGN __nv_bfloat16 g_ot_h[(size_t)NB * NPIX * CH];
__device__ BALIGN __nv_bfloat16 g_ot_l[(size_t)NB * NPIX * CH];
__device__ BALIGN __nv_bfloat16 g_wq_h[(size_t)3 * CH * CH];
__device__ BALIGN __nv_bfloat16 g_wq_l[(size_t)3 * CH * CH];
__device__ BALIGN __nv_bfloat16 g_wp_h[(size_t)CH * CH];
__device__ BALIGN __nv_bfloat16 g_wp_l[(size_t)CH * CH];
__device__ BALIGN float         g_attn[(size_t)NB * NPIX * NPIX];
__device__ float g_stats[NB * NGRP * 2];

// ---------------------------------------------------------------------------
// helpers
// ---------------------------------------------------------------------------
__device__ __forceinline__ uint32_t smem_u32(const void* p) {
    uint32_t a;
    asm("{ .reg .u64 t; cvta.to.shared.u64 t, %1; cvt.u32.u64 %0, t; }" : "=r"(a) : "l"(p));
    return a;
}
__device__ __forceinline__ void split_bf16(float v, __nv_bfloat16& h, __nv_bfloat16& l) {
    h = __float2bfloat16(v);
    l = __float2bfloat16(v - __bfloat162float(h));
}

#define CP16(sm, gp) asm volatile("cp.async.cg.shared.global [%0], [%1], 16;" :: "r"(sm), "l"(gp))
#define CP_COMMIT()  asm volatile("cp.async.commit_group;" ::: "memory")
#define CP_WAIT0()   asm volatile("cp.async.wait_group 0;" ::: "memory")
#define CP_WAIT1()   asm volatile("cp.async.wait_group 1;" ::: "memory")

#define LDSM4(r0, r1, r2, r3, a) \
    asm volatile("ldmatrix.sync.aligned.m8n8.x4.shared.b16 {%0,%1,%2,%3}, [%4];" \
                 : "=r"(r0), "=r"(r1), "=r"(r2), "=r"(r3) : "r"(a))

#define MMA_BF16(d, a, b0, b1) \
    asm volatile("mma.sync.aligned.m16n8k16.row.col.f32.bf16.bf16.f32 " \
                 "{%0,%1,%2,%3},{%4,%5,%6,%7},{%8,%9},{%0,%1,%2,%3};" \
                 : "+f"((d)[0]), "+f"((d)[1]), "+f"((d)[2]), "+f"((d)[3]) \
                 : "r"((a)[0]), "r"((a)[1]), "r"((a)[2]), "r"((a)[3]), "r"(b0), "r"(b1))

// ---------------------------------------------------------------------------
// GroupNorm phase 1: per-(b,g) mean / rstd
// ---------------------------------------------------------------------------
__global__ __launch_bounds__(256) void gn_stats_kernel(
    const float* __restrict__ x, float* __restrict__ stats)
{
    const int GSZ = (CH / NGRP) * NPIX;
    const int bg  = blockIdx.x;
    const float4* xv = (const float4*)(x + (size_t)bg * GSZ);
    const int tid = threadIdx.x;

    float s = 0.f, ss = 0.f;
    for (int i = tid; i < GSZ / 4; i += 256) {
        float4 v = xv[i];
        s  += v.x + v.y + v.z + v.w;
        ss += v.x * v.x + v.y * v.y + v.z * v.z + v.w * v.w;
    }
    __shared__ float rs[256], rss[256];
    rs[tid] = s; rss[tid] = ss;
    __syncthreads();
    for (int o = 128; o > 0; o >>= 1) {
        if (tid < o) { rs[tid] += rs[tid + o]; rss[tid] += rss[tid + o]; }
        __syncthreads();
    }
    if (tid == 0) {
        float mu  = rs[0] / GSZ;
        float var = rss[0] / GSZ - mu * mu;
        stats[bg * 2]     = mu;
        stats[bg * 2 + 1] = rsqrtf(var + 1e-5f);
    }
}

// ---------------------------------------------------------------------------
// GroupNorm phase 2: normalize + split + transpose -> ht[b][p][c]
// ---------------------------------------------------------------------------
__global__ __launch_bounds__(256) void gn_apply_kernel(
    const float* __restrict__ x, const float* __restrict__ gamma,
    const float* __restrict__ beta, const float* __restrict__ stats,
    __nv_bfloat16* __restrict__ hth, __nv_bfloat16* __restrict__ htl)
{
    __shared__ float s[32][33];
    const int p0 = blockIdx.x * 32, c0 = blockIdx.y * 32, b = blockIdx.z;
    const int tid = threadIdx.x;

    #pragma unroll
    for (int q = 0; q < 4; q++) {
        int ci = (tid >> 5) + q * 8, pj = tid & 31;
        int c = c0 + ci;
        float xv = x[((size_t)b * CH + c) * NPIX + p0 + pj];
        int g = c >> 4;
        float mu = stats[(b * NGRP + g) * 2], rinv = stats[(b * NGRP + g) * 2 + 1];
        s[ci][pj] = (xv - mu) * rinv * gamma[c] + beta[c];
    }
    __syncthreads();
    #pragma unroll
    for (int q = 0; q < 4; q++) {
        int cj = tid & 31, pi = (tid >> 5) + q * 8;
        __nv_bfloat16 h, l;
        split_bf16(s[cj][pi], h, l);
        size_t o = (size_t)b * NPIX * CH + (size_t)(p0 + pi) * CH + c0 + cj;
        hth[o] = h; htl[o] = l;
    }
}

// ---------------------------------------------------------------------------
// Row softmax -> split-bf16 P (warp-shuffle reductions, fast exp)
// ---------------------------------------------------------------------------
__global__ __launch_bounds__(256) void softmax_kernel(
    const float* __restrict__ attn,
    __nv_bfloat16* __restrict__ ph, __nv_bfloat16* __restrict__ pl)
{
    const size_t row = blockIdx.x;
    const float4* p = (const float4*)(attn + row * NPIX);
    const int tid = threadIdx.x;
    const int lane = tid & 31, wrp = tid >> 5;
    __shared__ float red[8];

    float4 v = p[tid];
    float m = fmaxf(fmaxf(v.x, v.y), fmaxf(v.z, v.w));
    #pragma unroll
    for (int o = 16; o > 0; o >>= 1) m = fmaxf(m, __shfl_xor_sync(~0u, m, o));
    if (lane == 0) red[wrp] = m;
    __syncthreads();
    float rmax = red[0];
    #pragma unroll
    for (int w = 1; w < 8; w++) rmax = fmaxf(rmax, red[w]);
    __syncthreads();

    v.x = __expf(v.x - rmax); v.y = __expf(v.y - rmax);
    v.z = __expf(v.z - rmax); v.w = __expf(v.w - rmax);
    float s = v.x + v.y + v.z + v.w;
    #pragma unroll
    for (int o = 16; o > 0; o >>= 1) s += __shfl_xor_sync(~0u, s, o);
    if (lane == 0) red[wrp] = s;
    __syncthreads();
    float tot = red[0];
    #pragma unroll
    for (int w = 1; w < 8; w++) tot += red[w];

    const float rinv = 1.f / tot;
    float vals[4] = {v.x * rinv, v.y * rinv, v.z * rinv, v.w * rinv};
    __nv_bfloat16 hh[4], ll[4];
    #pragma unroll
    for (int i = 0; i < 4; i++) split_bf16(vals[i], hh[i], ll[i]);
    size_t o = row * NPIX + tid * 4;
    *(__nv_bfloat162*)(ph + o)     = __nv_bfloat162(hh[0], hh[1]);
    *(__nv_bfloat162*)(ph + o + 2) = __nv_bfloat162(hh[2], hh[3]);
    *(__nv_bfloat162*)(pl + o)     = __nv_bfloat162(ll[0], ll[1]);
    *(__nv_bfloat162*)(pl + o + 2) = __nv_bfloat162(ll[2], ll[3]);
}

// ---------------------------------------------------------------------------
// fp32 -> split-bf16 (weights)
// ---------------------------------------------------------------------------
__global__ __launch_bounds__(256) void pack_kernel(
    const float* __restrict__ w,
    __nv_bfloat16* __restrict__ oh, __nv_bfloat16* __restrict__ ol, int n)
{
    int i = (blockIdx.x * 256 + threadIdx.x) * 2;
    if (i < n) {
        __nv_bfloat16 h0, l0, h1, l1;
        split_bf16(w[i], h0, l0);
        split_bf16(w[i + 1], h1, l1);
        *(__nv_bfloat162*)(oh + i) = __nv_bfloat162(h0, h1);
        *(__nv_bfloat162*)(ol + i) = __nv_bfloat162(l0, l1);
    }
}

// ---------------------------------------------------------------------------
// Split-bf16 HMMA GEMM: D[m][n] = sum_k A[m][k]*B[n][k]  (both k-major)
// CTA 128x128, BK=32, 8 warps (2M x 4N), warp tile 64x32, 3-stage cp.async,
// one __syncthreads per k-iter, 2 CTAs/SM.
// smem row = 128B: [hi 32 bf16 | lo 32 bf16], 16B units XOR-swizzled by row&7.
// EPI 0: QKV  1: scores  2: PV  3: proj(+bias+residual)
// ---------------------------------------------------------------------------
template<int EPI>
__global__ __launch_bounds__(256, 2) void tc_gemm(
    const __nv_bfloat16* __restrict__ Agh, const __nv_bfloat16* __restrict__ Agl,
    const __nv_bfloat16* __restrict__ Bgh, const __nv_bfloat16* __restrict__ Bgl,
    long long sAb, long long sBb, int ldA, int ldB, int K,
    const float* __restrict__ bias, float scale,
    float* __restrict__ outf,
    __nv_bfloat16* __restrict__ o0h, __nv_bfloat16* __restrict__ o0l,
    __nv_bfloat16* __restrict__ o1h, __nv_bfloat16* __restrict__ o1l,
    __nv_bfloat16* __restrict__ o2h, __nv_bfloat16* __restrict__ o2l,
    const float* __restrict__ resid)
{
    extern __shared__ char smem[];
    const uint32_t sb = smem_u32(smem);
    const int tid = threadIdx.x;
    const int lane = tid & 31, wid = tid >> 5;
    const int bz = blockIdx.z;
    const int m0 = blockIdx.y * TM;
    const int n0 = blockIdx.x * TN;

    const __nv_bfloat16* Ah = Agh + (size_t)bz * sAb + (size_t)m0 * ldA;
    const __nv_bfloat16* Al = Agl + (size_t)bz * sAb + (size_t)m0 * ldA;
    const __nv_bfloat16* Bh = Bgh + (size_t)bz * sBb + (size_t)n0 * ldB;
    const __nv_bfloat16* Bl = Bgl + (size_t)bz * sBb + (size_t)n0 * ldB;

    // loader mapping: row = tid>>1 (0..127), units (tid&1)*2 + {0,1}
    const int lrow = tid >> 1;
    const int lu0  = (tid & 1) * 2;
    const int lswz = lrow & 7;

    auto load_tile = [&](int buf, int k0) {
        const uint32_t sa  = sb + buf * STAGE_BYTES;
        const uint32_t sbB = sa + 16384;
        #pragma unroll
        for (int j = 0; j < 2; j++) {
            const int u = lu0 + j;
            const int gk = k0 + u * 8;
            CP16(sa  + lrow * 128 + ((u       ^ lswz) << 4), Ah + (size_t)lrow * ldA + gk);
            CP16(sa  + lrow * 128 + (((u + 4) ^ lswz) << 4), Al + (size_t)lrow * ldA + gk);
            CP16(sbB + lrow * 128 + ((u       ^ lswz) << 4), Bh + (size_t)lrow * ldB + gk);
            CP16(sbB + lrow * 128 + (((u + 4) ^ lswz) << 4), Bl + (size_t)lrow * ldB + gk);
        }
    };

    // warp layout: 2 (M) x 4 (N), warp tile 64x32
    const int wm = wid >> 2, wn = wid & 3;
    const int m_base = wm * 64, n_base = wn * 32;

    // ldmatrix lane mapping
    const int amat = lane >> 3;
    const int arow = (amat & 1) * 8 + (lane & 7);
    const int auadd = amat >> 1;
    const int bmat = lane >> 3;
    const int bnrow = (bmat >> 1) * 8 + (lane & 7);
    const int buadd = bmat & 1;

    float acc[4][4][4] = {};

    load_tile(0, 0);
    CP_COMMIT();
    load_tile(1, TK);
    CP_COMMIT();

    const int nk = K / TK;
    for (int i = 0; i < nk; i++) {
        if (i == nk - 1) { CP_WAIT0(); } else { CP_WAIT1(); }
        __syncthreads();
        if (i + 2 < nk) {
            load_tile((i + 2) % NSTAGE, (i + 2) * TK);
            CP_COMMIT();
        }
        const uint32_t sa  = sb + (i % NSTAGE) * STAGE_BYTES;
        const uint32_t sbB = sa + 16384;

        #pragma unroll
        for (int kk = 0; kk < 2; kk++) {
            // B fragments for the whole warp tile (16 regs live)
            uint32_t bh[8], bl[8];
            #pragma unroll
            for (int np = 0; np < 2; np++) {
                const int n = n_base + np * 16 + bnrow;
                const int rx = n & 7;
                const uint32_t base = sbB + n * 128;
                const int uh = kk * 2 + buadd;
                LDSM4(bh[np * 4 + 0], bh[np * 4 + 1], bh[np * 4 + 2], bh[np * 4 + 3],
                      base + ((uh ^ rx) << 4));
                LDSM4(bl[np * 4 + 0], bl[np * 4 + 1], bl[np * 4 + 2], bl[np * 4 + 3],
                      base + (((uh + 4) ^ rx) << 4));
            }
            // A fragments processed in 2 chunks of 2 mt to cap register pressure
            #pragma unroll
            for (int mc = 0; mc < 2; mc++) {
                uint32_t ah[2][4], al[2][4];
                #pragma unroll
                for (int m2 = 0; m2 < 2; m2++) {
                    const int mt = mc * 2 + m2;
                    const int row = m_base + mt * 16 + arow;
                    const int rx = row & 7;
                    const uint32_t base = sa + row * 128;
                    const int uh = kk * 2 + auadd;
                    LDSM4(ah[m2][0], ah[m2][1], ah[m2][2], ah[m2][3],
                          base + ((uh ^ rx) << 4));
                    LDSM4(al[m2][0], al[m2][1], al[m2][2], al[m2][3],
                          base + (((uh + 4) ^ rx) << 4));
                }
                #pragma unroll
                for (int m2 = 0; m2 < 2; m2++) {
                    const int mt = mc * 2 + m2;
                    #pragma unroll
                    for (int nt = 0; nt < 4; nt++) {
                        const int r = (nt >> 1) * 4 + (nt & 1) * 2;
                        MMA_BF16(acc[mt][nt], ah[m2], bh[r], bh[r + 1]);
                        MMA_BF16(acc[mt][nt], ah[m2], bl[r], bl[r + 1]);
                        MMA_BF16(acc[mt][nt], al[m2], bh[r], bh[r + 1]);
                    }
                }
            }
        }
    }

    // ---- stage accumulators to smem fp32 (reuse pipeline smem) ----
    __syncthreads();
    float* s = (float*)smem;
    #pragma unroll
    for (int mt = 0; mt < 4; mt++)
        #pragma unroll
        for (int nt = 0; nt < 4; nt++)
            #pragma unroll
            for (int r = 0; r < 4; r++) {
                const int row = m_base + mt * 16 + (lane >> 2) + (r >= 2 ? 8 : 0);
                const int col = n_base + nt * 8 + (lane & 3) * 2 + (r & 1);
                s[row * SPITCH + col] = acc[mt][nt][r];
            }
    __syncthreads();

    // ---- writers ----
    if (EPI == 0 && m0 < 2 * CH) {
        // Q or K tile: [p][c] output, m-fast pairs for coalescing over c
        __nv_bfloat16* dh = (m0 < CH ? o0h : o1h) + (size_t)bz * NPIX * CH;
        __nv_bfloat16* dl = (m0 < CH ? o0l : o1l) + (size_t)bz * NPIX * CH;
        const int coff = m0 & (CH - 1);
        for (int it = 0; it < 32; it++) {
            const int idx = it * 512 + tid * 2;
            const int n = idx >> 7, m = idx & 127;
            float v0 = s[m * SPITCH + n] + bias[m0 + m];
            float v1 = s[(m + 1) * SPITCH + n] + bias[m0 + m + 1];
            __nv_bfloat16 h0, l0, h1, l1;
            split_bf16(v0, h0, l0); split_bf16(v1, h1, l1);
            const size_t o = (size_t)(n0 + n) * CH + coff + m;
            *(__nv_bfloat162*)(dh + o) = __nv_bfloat162(h0, h1);
            *(__nv_bfloat162*)(dl + o) = __nv_bfloat162(l0, l1);
        }
    } else {
        for (int it = 0; it < 32; it++) {
            const int idx = it * 512 + tid * 2;
            const int m = idx >> 7, n = idx & 127;
            float v0 = s[m * SPITCH + n];
            float v1 = s[m * SPITCH + n + 1];
            if (EPI == 0) {          // V tile -> v[b][c][p]
                const int c = m0 - 2 * CH + m;
                v0 += bias[m0 + m]; v1 += bias[m0 + m];
                __nv_bfloat16 h0, l0, h1, l1;
                split_bf16(v0, h0, l0); split_bf16(v1, h1, l1);
                const size_t o = ((size_t)bz * CH + c) * NPIX + n0 + n;
                *(__nv_bfloat162*)(o2h + o) = __nv_bfloat162(h0, h1);
                *(__nv_bfloat162*)(o2l + o) = __nv_bfloat162(l0, l1);
            } else if (EPI == 1) {   // scores fp32
                const size_t o = ((size_t)bz * NPIX + m0 + m) * NPIX + n0 + n;
                *(float2*)(outf + o) = make_float2(v0 * scale, v1 * scale);
            } else if (EPI == 2) {   // Ot split [p][c]
                __nv_bfloat16 h0, l0, h1, l1;
                split_bf16(v0, h0, l0); split_bf16(v1, h1, l1);
                const size_t o = ((size_t)bz * NPIX + m0 + m) * CH + n0 + n;
                *(__nv_bfloat162*)(o0h + o) = __nv_bfloat162(h0, h1);
                *(__nv_bfloat162*)(o0l + o) = __nv_bfloat162(l0, l1);
            } else {                 // proj + bias + residual
                const float bv = bias[m0 + m];
                const size_t o = ((size_t)bz * CH + m0 + m) * NPIX + n0 + n;
                float2 rv = *(const float2*)(resid + o);
                *(float2*)(outf + o) = make_float2(v0 + bv + rv.x, v1 + bv + rv.y);
            }
        }
    }
}

// ---------------------------------------------------------------------------
extern "C" void kernel_launch(void* const* d_in, const int* in_sizes, int n_in,
                              void* d_out, int out_size)
{
    const float* x      = (const float*)d_in[0];
    const float* gamma  = (const float*)d_in[1];
    const float* beta   = (const float*)d_in[2];
    const float* w_qkv  = (const float*)d_in[3];
    const float* b_qkv  = (const float*)d_in[4];
    const float* w_proj = (const float*)d_in[5];
    const float* b_proj = (const float*)d_in[6];
    float* out = (float*)d_out;

    __nv_bfloat16 *hth, *htl, *qh, *ql, *kh, *kl, *vh, *vl, *ph, *pl,
                  *oth, *otl, *wqh, *wql, *wph, *wpl;
    float *attn, *stats;
    cudaGetSymbolAddress((void**)&hth, g_ht_h); cudaGetSymbolAddress((void**)&htl, g_ht_l);
    cudaGetSymbolAddress((void**)&qh,  g_q_h ); cudaGetSymbolAddress((void**)&ql,  g_q_l );
    cudaGetSymbolAddress((void**)&kh,  g_k_h ); cudaGetSymbolAddress((void**)&kl,  g_k_l );
    cudaGetSymbolAddress((void**)&vh,  g_v_h ); cudaGetSymbolAddress((void**)&vl,  g_v_l );
    cudaGetSymbolAddress((void**)&ph,  g_p_h ); cudaGetSymbolAddress((void**)&pl,  g_p_l );
    cudaGetSymbolAddress((void**)&oth, g_ot_h); cudaGetSymbolAddress((void**)&otl, g_ot_l);
    cudaGetSymbolAddress((void**)&wqh, g_wq_h); cudaGetSymbolAddress((void**)&wql, g_wq_l);
    cudaGetSymbolAddress((void**)&wph, g_wp_h); cudaGetSymbolAddress((void**)&wpl, g_wp_l);
    cudaGetSymbolAddress((void**)&attn, g_attn);
    cudaGetSymbolAddress((void**)&stats, g_stats);

    cudaFuncSetAttribute(tc_gemm<0>, cudaFuncAttributeMaxDynamicSharedMemorySize, SMEM_BYTES);
    cudaFuncSetAttribute(tc_gemm<1>, cudaFuncAttributeMaxDynamicSharedMemorySize, SMEM_BYTES);
    cudaFuncSetAttribute(tc_gemm<2>, cudaFuncAttributeMaxDynamicSharedMemorySize, SMEM_BYTES);
    cudaFuncSetAttribute(tc_gemm<3>, cudaFuncAttributeMaxDynamicSharedMemorySize, SMEM_BYTES);

    const long long sH = (long long)NPIX * CH;
    const long long sP = (long long)NPIX * NPIX;

    pack_kernel<<<(3 * CH * CH / 2 + 255) / 256, 256>>>(w_qkv, wqh, wql, 3 * CH * CH);
    pack_kernel<<<(CH * CH / 2 + 255) / 256, 256>>>(w_proj, wph, wpl, CH * CH);
    gn_stats_kernel<<<NB * NGRP, 256>>>(x, stats);
    gn_apply_kernel<<<dim3(NPIX / 32, CH / 32, NB), 256>>>(x, gamma, beta, stats, hth, htl);

    // QKV: A = w_qkv [1536,512], B = ht[b][p][c] -> q/k [p][c], v [c][p]
    tc_gemm<0><<<dim3(NPIX / TN, 1536 / TM, NB), 256, SMEM_BYTES>>>(
        wqh, wql, hth, htl, 0, sH, CH, CH, CH,
        b_qkv, 1.f, nullptr, qh, ql, kh, kl, vh, vl, nullptr);

    // scores: q[i][c] . k[j][c] * scale -> attn fp32
    tc_gemm<1><<<dim3(NPIX / TN, NPIX / TM, NB), 256, SMEM_BYTES>>>(
        qh, ql, kh, kl, sH, sH, CH, CH, CH,
        nullptr, 1.0f / sqrtf((float)CH), attn,
        nullptr, nullptr, nullptr, nullptr, nullptr, nullptr, nullptr);

    softmax_kernel<<<NB * NPIX, 256>>>(attn, ph, pl);

    // PV: p[i][j] . v[c][j] -> ot[p][c]
    tc_gemm<2><<<dim3(CH / TN, NPIX / TM, NB), 256, SMEM_BYTES>>>(
        ph, pl, vh, vl, sP, sH, NPIX, NPIX, NPIX,
        nullptr, 1.f, nullptr, oth, otl,
        nullptr, nullptr, nullptr, nullptr, nullptr);

    // proj: w_proj[o][c] . ot[p][c] + bias + residual -> out [b][c][p]
    tc_gemm<3><<<dim3(NPIX / TN, CH / TM, NB), 256, SMEM_BYTES>>>(
        wph, wpl, oth, otl, 0, sH, CH, CH, CH,
        b_proj, 1.f, out, nullptr, nullptr, nullptr, nullptr, nullptr, nullptr, x);
}

// round 8
// speedup vs baseline: 1.4073x; 1.0001x over previous
#include <cuda_runtime.h>
#include <cuda_bf16.h>
#include <math.h>
#include <stdint.h>

// ---------------------------------------------------------------------------
// Problem constants
// ---------------------------------------------------------------------------
constexpr int NB   = 16;
constexpr int CH   = 512;
constexpr int NPIX = 1024;
constexpr int NGRP = 32;

// GEMM tiling: CTA 128x128, BK=32, 8 warps (2M x 4N), warp tile 64x32
constexpr int TM = 128, TN = 128, TK = 32;

constexpr int STAGE_BYTES = 32768;                  // A 16KB + B 16KB
constexpr int NSTAGE      = 3;
constexpr int SPITCH      = 129;                    // fp32 epilogue pitch
constexpr int SMEM_BYTES  = NSTAGE * STAGE_BYTES;   // 98304 (>= 128*129*4)

// ---------------------------------------------------------------------------
// Scratch (__device__ globals; allocation-free rule). hi/lo split-bf16 pairs.
// ---------------------------------------------------------------------------
#define BALIGN __align__(256)
__device__ BALIGN __nv_bfloat16 g_ht_h[(size_t)NB * NPIX * CH];
__device__ BALIGN __nv_bfloat16 g_ht_l[(size_t)NB * NPIX * CH];
__device__ BALIGN __nv_bfloat16 g_q_h [(size_t)NB * NPIX * CH];
__device__ BALIGN __nv_bfloat16 g_q_l [(size_t)NB * NPIX * CH];
__device__ BALIGN __nv_bfloat16 g_k_h [(size_t)NB * NPIX * CH];
__device__ BALIGN __nv_bfloat16 g_k_l [(size_t)NB * NPIX * CH];
__device__ BALIGN __nv_bfloat16 g_v_h [(size_t)NB * CH * NPIX];
__device__ BALIGN __nv_bfloat16 g_v_l [(size_t)NB * CH * NPIX];
__device__ BALIGN __nv_bfloat16 g_p_h [(size_t)NB * NPIX * NPIX];
__device__ BALIGN __nv_bfloat16 g_p_l [(size_t)NB * NPIX * NPIX];
__device__ BALIGN __nv_bfloat16 g_ot_h[(size_t)NB * NPIX * CH];
__device__ BALIGN __nv_bfloat16 g_ot_l[(size_t)NB * NPIX * CH];
__device__ BALIGN __nv_bfloat16 g_wq_h[(size_t)3 * CH * CH];
__device__ BALIGN __nv_bfloat16 g_wq_l[(size_t)3 * CH * CH];
__device__ BALIGN __nv_bfloat16 g_wp_h[(size_t)CH * CH];
__device__ BALIGN __nv_bfloat16 g_wp_l[(size_t)CH * CH];
__device__ BALIGN float         g_attn[(size_t)NB * NPIX * NPIX];
__device__ float g_stats[NB * NGRP * 2];

// ---------------------------------------------------------------------------
// helpers
// ---------------------------------------------------------------------------
__device__ __forceinline__ uint32_t smem_u32(const void* p) {
    uint32_t a;
    asm("{ .reg .u64 t; cvta.to.shared.u64 t, %1; cvt.u32.u64 %0, t; }" : "=r"(a) : "l"(p));
    return a;
}
__device__ __forceinline__ void split_bf16(float v, __nv_bfloat16& h, __nv_bfloat16& l) {
    h = __float2bfloat16(v);
    l = __float2bfloat16(v - __bfloat162float(h));
}

#define CP16(sm, gp) asm volatile("cp.async.cg.shared.global [%0], [%1], 16;" :: "r"(sm), "l"(gp))
#define CP_COMMIT()  asm volatile("cp.async.commit_group;" ::: "memory")
#define CP_WAIT0()   asm volatile("cp.async.wait_group 0;" ::: "memory")
#define CP_WAIT1()   asm volatile("cp.async.wait_group 1;" ::: "memory")

#define LDSM4(r0, r1, r2, r3, a) \
    asm volatile("ldmatrix.sync.aligned.m8n8.x4.shared.b16 {%0,%1,%2,%3}, [%4];" \
                 : "=r"(r0), "=r"(r1), "=r"(r2), "=r"(r3) : "r"(a))

#define MMA_BF16(d, a, b0, b1) \
    asm volatile("mma.sync.aligned.m16n8k16.row.col.f32.bf16.bf16.f32 " \
                 "{%0,%1,%2,%3},{%4,%5,%6,%7},{%8,%9},{%0,%1,%2,%3};" \
                 : "+f"((d)[0]), "+f"((d)[1]), "+f"((d)[2]), "+f"((d)[3]) \
                 : "r"((a)[0]), "r"((a)[1]), "r"((a)[2]), "r"((a)[3]), "r"(b0), "r"(b1))

// ---------------------------------------------------------------------------
// GroupNorm phase 1: per-(b,g) mean / rstd
// ---------------------------------------------------------------------------
__global__ __launch_bounds__(256) void gn_stats_kernel(
    const float* __restrict__ x, float* __restrict__ stats)
{
    const int GSZ = (CH / NGRP) * NPIX;
    const int bg  = blockIdx.x;
    const float4* xv = (const float4*)(x + (size_t)bg * GSZ);
    const int tid = threadIdx.x;

    float s = 0.f, ss = 0.f;
    for (int i = tid; i < GSZ / 4; i += 256) {
        float4 v = xv[i];
        s  += v.x + v.y + v.z + v.w;
        ss += v.x * v.x + v.y * v.y + v.z * v.z + v.w * v.w;
    }
    __shared__ float rs[256], rss[256];
    rs[tid] = s; rss[tid] = ss;
    __syncthreads();
    for (int o = 128; o > 0; o >>= 1) {
        if (tid < o) { rs[tid] += rs[tid + o]; rss[tid] += rss[tid + o]; }
        __syncthreads();
    }
    if (tid == 0) {
        float mu  = rs[0] / GSZ;
        float var = rss[0] / GSZ - mu * mu;
        stats[bg * 2]     = mu;
        stats[bg * 2 + 1] = rsqrtf(var + 1e-5f);
    }
}

// ---------------------------------------------------------------------------
// GroupNorm phase 2: normalize + split + transpose -> ht[b][p][c]
// ---------------------------------------------------------------------------
__global__ __launch_bounds__(256) void gn_apply_kernel(
    const float* __restrict__ x, const float* __restrict__ gamma,
    const float* __restrict__ beta, const float* __restrict__ stats,
    __nv_bfloat16* __restrict__ hth, __nv_bfloat16* __restrict__ htl)
{
    __shared__ float s[32][33];
    const int p0 = blockIdx.x * 32, c0 = blockIdx.y * 32, b = blockIdx.z;
    const int tid = threadIdx.x;

    #pragma unroll
    for (int q = 0; q < 4; q++) {
        int ci = (tid >> 5) + q * 8, pj = tid & 31;
        int c = c0 + ci;
        float xv = x[((size_t)b * CH + c) * NPIX + p0 + pj];
        int g = c >> 4;
        float mu = stats[(b * NGRP + g) * 2], rinv = stats[(b * NGRP + g) * 2 + 1];
        s[ci][pj] = (xv - mu) * rinv * gamma[c] + beta[c];
    }
    __syncthreads();
    #pragma unroll
    for (int q = 0; q < 4; q++) {
        int cj = tid & 31, pi = (tid >> 5) + q * 8;
        __nv_bfloat16 h, l;
        split_bf16(s[cj][pi], h, l);
        size_t o = (size_t)b * NPIX * CH + (size_t)(p0 + pi) * CH + c0 + cj;
        hth[o] = h; htl[o] = l;
    }
}

// ---------------------------------------------------------------------------
// Row softmax -> split-bf16 P (warp-shuffle reductions, fast exp)
// ---------------------------------------------------------------------------
__global__ __launch_bounds__(256) void softmax_kernel(
    const float* __restrict__ attn,
    __nv_bfloat16* __restrict__ ph, __nv_bfloat16* __restrict__ pl)
{
    const size_t row = blockIdx.x;
    const float4* p = (const float4*)(attn + row * NPIX);
    const int tid = threadIdx.x;
    const int lane = tid & 31, wrp = tid >> 5;
    __shared__ float red[8];

    float4 v = p[tid];
    float m = fmaxf(fmaxf(v.x, v.y), fmaxf(v.z, v.w));
    #pragma unroll
    for (int o = 16; o > 0; o >>= 1) m = fmaxf(m, __shfl_xor_sync(~0u, m, o));
    if (lane == 0) red[wrp] = m;
    __syncthreads();
    float rmax = red[0];
    #pragma unroll
    for (int w = 1; w < 8; w++) rmax = fmaxf(rmax, red[w]);
    __syncthreads();

    v.x = __expf(v.x - rmax); v.y = __expf(v.y - rmax);
    v.z = __expf(v.z - rmax); v.w = __expf(v.w - rmax);
    float s = v.x + v.y + v.z + v.w;
    #pragma unroll
    for (int o = 16; o > 0; o >>= 1) s += __shfl_xor_sync(~0u, s, o);
    if (lane == 0) red[wrp] = s;
    __syncthreads();
    float tot = red[0];
    #pragma unroll
    for (int w = 1; w < 8; w++) tot += red[w];

    const float rinv = 1.f / tot;
    float vals[4] = {v.x * rinv, v.y * rinv, v.z * rinv, v.w * rinv};
    __nv_bfloat16 hh[4], ll[4];
    #pragma unroll
    for (int i = 0; i < 4; i++) split_bf16(vals[i], hh[i], ll[i]);
    size_t o = row * NPIX + tid * 4;
    *(__nv_bfloat162*)(ph + o)     = __nv_bfloat162(hh[0], hh[1]);
    *(__nv_bfloat162*)(ph + o + 2) = __nv_bfloat162(hh[2], hh[3]);
    *(__nv_bfloat162*)(pl + o)     = __nv_bfloat162(ll[0], ll[1]);
    *(__nv_bfloat162*)(pl + o + 2) = __nv_bfloat162(ll[2], ll[3]);
}

// ---------------------------------------------------------------------------
// fp32 -> split-bf16 (weights)
// ---------------------------------------------------------------------------
__global__ __launch_bounds__(256) void pack_kernel(
    const float* __restrict__ w,
    __nv_bfloat16* __restrict__ oh, __nv_bfloat16* __restrict__ ol, int n)
{
    int i = (blockIdx.x * 256 + threadIdx.x) * 2;
    if (i < n) {
        __nv_bfloat16 h0, l0, h1, l1;
        split_bf16(w[i], h0, l0);
        split_bf16(w[i + 1], h1, l1);
        *(__nv_bfloat162*)(oh + i) = __nv_bfloat162(h0, h1);
        *(__nv_bfloat162*)(ol + i) = __nv_bfloat162(l0, l1);
    }
}

// ---------------------------------------------------------------------------
// Split-bf16 HMMA GEMM: D[m][n] = sum_k A[m][k]*B[n][k]  (both k-major)
// CTA 128x128, BK=32, 8 warps (2M x 4N), warp tile 64x32, 3-stage cp.async,
// one __syncthreads per k-iter, 2 CTAs/SM.
// Term-outer MMA schedule: 8 independent MMAs between accumulator reuses.
// smem row = 128B: [hi 32 bf16 | lo 32 bf16], 16B units XOR-swizzled by row&7.
// EPI 0: QKV  1: scores  2: PV  3: proj(+bias+residual)
// ---------------------------------------------------------------------------
template<int EPI>
__global__ __launch_bounds__(256, 2) void tc_gemm(
    const __nv_bfloat16* __restrict__ Agh, const __nv_bfloat16* __restrict__ Agl,
    const __nv_bfloat16* __restrict__ Bgh, const __nv_bfloat16* __restrict__ Bgl,
    long long sAb, long long sBb, int ldA, int ldB, int K,
    const float* __restrict__ bias, float scale,
    float* __restrict__ outf,
    __nv_bfloat16* __restrict__ o0h, __nv_bfloat16* __restrict__ o0l,
    __nv_bfloat16* __restrict__ o1h, __nv_bfloat16* __restrict__ o1l,
    __nv_bfloat16* __restrict__ o2h, __nv_bfloat16* __restrict__ o2l,
    const float* __restrict__ resid)
{
    extern __shared__ char smem[];
    const uint32_t sb = smem_u32(smem);
    const int tid = threadIdx.x;
    const int lane = tid & 31, wid = tid >> 5;
    const int bz = blockIdx.z;
    const int m0 = blockIdx.y * TM;
    const int n0 = blockIdx.x * TN;

    const __nv_bfloat16* Ah = Agh + (size_t)bz * sAb + (size_t)m0 * ldA;
    const __nv_bfloat16* Al = Agl + (size_t)bz * sAb + (size_t)m0 * ldA;
    const __nv_bfloat16* Bh = Bgh + (size_t)bz * sBb + (size_t)n0 * ldB;
    const __nv_bfloat16* Bl = Bgl + (size_t)bz * sBb + (size_t)n0 * ldB;

    // loader mapping: row = tid>>1 (0..127), units (tid&1)*2 + {0,1}
    const int lrow = tid >> 1;
    const int lu0  = (tid & 1) * 2;
    const int lswz = lrow & 7;

    auto load_tile = [&](int buf, int k0) {
        const uint32_t sa  = sb + buf * STAGE_BYTES;
        const uint32_t sbB = sa + 16384;
        #pragma unroll
        for (int j = 0; j < 2; j++) {
            const int u = lu0 + j;
            const int gk = k0 + u * 8;
            CP16(sa  + lrow * 128 + ((u       ^ lswz) << 4), Ah + (size_t)lrow * ldA + gk);
            CP16(sa  + lrow * 128 + (((u + 4) ^ lswz) << 4), Al + (size_t)lrow * ldA + gk);
            CP16(sbB + lrow * 128 + ((u       ^ lswz) << 4), Bh + (size_t)lrow * ldB + gk);
            CP16(sbB + lrow * 128 + (((u + 4) ^ lswz) << 4), Bl + (size_t)lrow * ldB + gk);
        }
    };

    // warp layout: 2 (M) x 4 (N), warp tile 64x32
    const int wm = wid >> 2, wn = wid & 3;
    const int m_base = wm * 64, n_base = wn * 32;

    // ldmatrix lane mapping
    const int amat = lane >> 3;
    const int arow = (amat & 1) * 8 + (lane & 7);
    const int auadd = amat >> 1;
    const int bmat = lane >> 3;
    const int bnrow = (bmat >> 1) * 8 + (lane & 7);
    const int buadd = bmat & 1;

    float acc[4][4][4] = {};

    load_tile(0, 0);
    CP_COMMIT();
    load_tile(1, TK);
    CP_COMMIT();

    const int nk = K / TK;
    for (int i = 0; i < nk; i++) {
        if (i == nk - 1) { CP_WAIT0(); } else { CP_WAIT1(); }
        __syncthreads();
        if (i + 2 < nk) {
            load_tile((i + 2) % NSTAGE, (i + 2) * TK);
            CP_COMMIT();
        }
        const uint32_t sa  = sb + (i % NSTAGE) * STAGE_BYTES;
        const uint32_t sbB = sa + 16384;

        #pragma unroll
        for (int kk = 0; kk < 2; kk++) {
            // B fragments for the whole warp tile (16 regs live)
            uint32_t bh[8], bl[8];
            #pragma unroll
            for (int np = 0; np < 2; np++) {
                const int n = n_base + np * 16 + bnrow;
                const int rx = n & 7;
                const uint32_t base = sbB + n * 128;
                const int uh = kk * 2 + buadd;
                LDSM4(bh[np * 4 + 0], bh[np * 4 + 1], bh[np * 4 + 2], bh[np * 4 + 3],
                      base + ((uh ^ rx) << 4));
                LDSM4(bl[np * 4 + 0], bl[np * 4 + 1], bl[np * 4 + 2], bl[np * 4 + 3],
                      base + (((uh + 4) ^ rx) << 4));
            }
            // A fragments processed in 2 chunks of 2 mt to cap register pressure.
            // Term-outer schedule: all 8 (m2,nt) MMAs of one term issue before the
            // next term touches the same accumulators -> no back-to-back acc RAW.
            #pragma unroll
            for (int mc = 0; mc < 2; mc++) {
                uint32_t ah[2][4], al[2][4];
                #pragma unroll
                for (int m2 = 0; m2 < 2; m2++) {
                    const int mt = mc * 2 + m2;
                    const int row = m_base + mt * 16 + arow;
                    const int rx = row & 7;
                    const uint32_t base = sa + row * 128;
                    const int uh = kk * 2 + auadd;
                    LDSM4(ah[m2][0], ah[m2][1], ah[m2][2], ah[m2][3],
                          base + ((uh ^ rx) << 4));
                    LDSM4(al[m2][0], al[m2][1], al[m2][2], al[m2][3],
                          base + (((uh + 4) ^ rx) << 4));
                }
                // term 0: ah x bh
                #pragma unroll
                for (int m2 = 0; m2 < 2; m2++)
                    #pragma unroll
                    for (int nt = 0; nt < 4; nt++) {
                        const int r = (nt >> 1) * 4 + (nt & 1) * 2;
                        MMA_BF16(acc[mc * 2 + m2][nt], ah[m2], bh[r], bh[r + 1]);
                    }
                // term 1: ah x bl
                #pragma unroll
                for (int m2 = 0; m2 < 2; m2++)
                    #pragma unroll
                    for (int nt = 0; nt < 4; nt++) {
                        const int r = (nt >> 1) * 4 + (nt & 1) * 2;
                        MMA_BF16(acc[mc * 2 + m2][nt], ah[m2], bl[r], bl[r + 1]);
                    }
                // term 2: al x bh
                #pragma unroll
                for (int m2 = 0; m2 < 2; m2++)
                    #pragma unroll
                    for (int nt = 0; nt < 4; nt++) {
                        const int r = (nt >> 1) * 4 + (nt & 1) * 2;
                        MMA_BF16(acc[mc * 2 + m2][nt], al[m2], bh[r], bh[r + 1]);
                    }
            }
        }
    }

    // ---- stage accumulators to smem fp32 (reuse pipeline smem) ----
    __syncthreads();
    float* s = (float*)smem;
    #pragma unroll
    for (int mt = 0; mt < 4; mt++)
        #pragma unroll
        for (int nt = 0; nt < 4; nt++)
            #pragma unroll
            for (int r = 0; r < 4; r++) {
                const int row = m_base + mt * 16 + (lane >> 2) + (r >= 2 ? 8 : 0);
                const int col = n_base + nt * 8 + (lane & 3) * 2 + (r & 1);
                s[row * SPITCH + col] = acc[mt][nt][r];
            }
    __syncthreads();

    // ---- writers ----
    if (EPI == 0 && m0 < 2 * CH) {
        // Q or K tile: [p][c] output, m-fast pairs for coalescing over c
        __nv_bfloat16* dh = (m0 < CH ? o0h : o1h) + (size_t)bz * NPIX * CH;
        __nv_bfloat16* dl = (m0 < CH ? o0l : o1l) + (size_t)bz * NPIX * CH;
        const int coff = m0 & (CH - 1);
        for (int it = 0; it < 32; it++) {
            const int idx = it * 512 + tid * 2;
            const int n = idx >> 7, m = idx & 127;
            float v0 = s[m * SPITCH + n] + bias[m0 + m];
            float v1 = s[(m + 1) * SPITCH + n] + bias[m0 + m + 1];
            __nv_bfloat16 h0, l0, h1, l1;
            split_bf16(v0, h0, l0); split_bf16(v1, h1, l1);
            const size_t o = (size_t)(n0 + n) * CH + coff + m;
            *(__nv_bfloat162*)(dh + o) = __nv_bfloat162(h0, h1);
            *(__nv_bfloat162*)(dl + o) = __nv_bfloat162(l0, l1);
        }
    } else {
        for (int it = 0; it < 32; it++) {
            const int idx = it * 512 + tid * 2;
            const int m = idx >> 7, n = idx & 127;
            float v0 = s[m * SPITCH + n];
            float v1 = s[m * SPITCH + n + 1];
            if (EPI == 0) {          // V tile -> v[b][c][p]
                const int c = m0 - 2 * CH + m;
                v0 += bias[m0 + m]; v1 += bias[m0 + m];
                __nv_bfloat16 h0, l0, h1, l1;
                split_bf16(v0, h0, l0); split_bf16(v1, h1, l1);
                const size_t o = ((size_t)bz * CH + c) * NPIX + n0 + n;
                *(__nv_bfloat162*)(o2h + o) = __nv_bfloat162(h0, h1);
                *(__nv_bfloat162*)(o2l + o) = __nv_bfloat162(l0, l1);
            } else if (EPI == 1) {   // scores fp32
                const size_t o = ((size_t)bz * NPIX + m0 + m) * NPIX + n0 + n;
                *(float2*)(outf + o) = make_float2(v0 * scale, v1 * scale);
            } else if (EPI == 2) {   // Ot split [p][c]
                __nv_bfloat16 h0, l0, h1, l1;
                split_bf16(v0, h0, l0); split_bf16(v1, h1, l1);
                const size_t o = ((size_t)bz * NPIX + m0 + m) * CH + n0 + n;
                *(__nv_bfloat162*)(o0h + o) = __nv_bfloat162(h0, h1);
                *(__nv_bfloat162*)(o0l + o) = __nv_bfloat162(l0, l1);
            } else {                 // proj + bias + residual
                const float bv = bias[m0 + m];
                const size_t o = ((size_t)bz * CH + m0 + m) * NPIX + n0 + n;
                float2 rv = *(const float2*)(resid + o);
                *(float2*)(outf + o) = make_float2(v0 + bv + rv.x, v1 + bv + rv.y);
            }
        }
    }
}

// ---------------------------------------------------------------------------
extern "C" void kernel_launch(void* const* d_in, const int* in_sizes, int n_in,
                              void* d_out, int out_size)
{
    const float* x      = (const float*)d_in[0];
    const float* gamma  = (const float*)d_in[1];
    const float* beta   = (const float*)d_in[2];
    const float* w_qkv  = (const float*)d_in[3];
    const float* b_qkv  = (const float*)d_in[4];
    const float* w_proj = (const float*)d_in[5];
    const float* b_proj = (const float*)d_in[6];
    float* out = (float*)d_out;

    __nv_bfloat16 *hth, *htl, *qh, *ql, *kh, *kl, *vh, *vl, *ph, *pl,
                  *oth, *otl, *wqh, *wql, *wph, *wpl;
    float *attn, *stats;
    cudaGetSymbolAddress((void**)&hth, g_ht_h); cudaGetSymbolAddress((void**)&htl, g_ht_l);
    cudaGetSymbolAddress((void**)&qh,  g_q_h ); cudaGetSymbolAddress((void**)&ql,  g_q_l );
    cudaGetSymbolAddress((void**)&kh,  g_k_h ); cudaGetSymbolAddress((void**)&kl,  g_k_l );
    cudaGetSymbolAddress((void**)&vh,  g_v_h ); cudaGetSymbolAddress((void**)&vl,  g_v_l );
    cudaGetSymbolAddress((void**)&ph,  g_p_h ); cudaGetSymbolAddress((void**)&pl,  g_p_l );
    cudaGetSymbolAddress((void**)&oth, g_ot_h); cudaGetSymbolAddress((void**)&otl, g_ot_l);
    cudaGetSymbolAddress((void**)&wqh, g_wq_h); cudaGetSymbolAddress((void**)&wql, g_wq_l);
    cudaGetSymbolAddress((void**)&wph, g_wp_h); cudaGetSymbolAddress((void**)&wpl, g_wp_l);
    cudaGetSymbolAddress((void**)&attn, g_attn);
    cudaGetSymbolAddress((void**)&stats, g_stats);

    cudaFuncSetAttribute(tc_gemm<0>, cudaFuncAttributeMaxDynamicSharedMemorySize, SMEM_BYTES);
    cudaFuncSetAttribute(tc_gemm<1>, cudaFuncAttributeMaxDynamicSharedMemorySize, SMEM_BYTES);
    cudaFuncSetAttribute(tc_gemm<2>, cudaFuncAttributeMaxDynamicSharedMemorySize, SMEM_BYTES);
    cudaFuncSetAttribute(tc_gemm<3>, cudaFuncAttributeMaxDynamicSharedMemorySize, SMEM_BYTES);

    const long long sH = (long long)NPIX * CH;
    const long long sP = (long long)NPIX * NPIX;

    pack_kernel<<<(3 * CH * CH / 2 + 255) / 256, 256>>>(w_qkv, wqh, wql, 3 * CH * CH);
    pack_kernel<<<(CH * CH / 2 + 255) / 256, 256>>>(w_proj, wph, wpl, CH * CH);
    gn_stats_kernel<<<NB * NGRP, 256>>>(x, stats);
    gn_apply_kernel<<<dim3(NPIX / 32, CH / 32, NB), 256>>>(x, gamma, beta, stats, hth, htl);

    // QKV: A = w_qkv [1536,512], B = ht[b][p][c] -> q/k [p][c], v [c][p]
    tc_gemm<0><<<dim3(NPIX / TN, 1536 / TM, NB), 256, SMEM_BYTES>>>(
        wqh, wql, hth, htl, 0, sH, CH, CH, CH,
        b_qkv, 1.f, nullptr, qh, ql, kh, kl, vh, vl, nullptr);

    // scores: q[i][c] . k[j][c] * scale -> attn fp32
    tc_gemm<1><<<dim3(NPIX / TN, NPIX / TM, NB), 256, SMEM_BYTES>>>(
        qh, ql, kh, kl, sH, sH, CH, CH, CH,
        nullptr, 1.0f / sqrtf((float)CH), attn,
        nullptr, nullptr, nullptr, nullptr, nullptr, nullptr, nullptr);

    softmax_kernel<<<NB * NPIX, 256>>>(attn, ph, pl);

    // PV: p[i][j] . v[c][j] -> ot[p][c]
    tc_gemm<2><<<dim3(CH / TN, NPIX / TM, NB), 256, SMEM_BYTES>>>(
        ph, pl, vh, vl, sP, sH, NPIX, NPIX, NPIX,
        nullptr, 1.f, nullptr, oth, otl,
        nullptr, nullptr, nullptr, nullptr, nullptr);

    // proj: w_proj[o][c] . ot[p][c] + bias + residual -> out [b][c][p]
    tc_gemm<3><<<dim3(NPIX / TN, CH / TM, NB), 256, SMEM_BYTES>>>(
        wph, wpl, oth, otl, 0, sH, CH, CH, CH,
        b_proj, 1.f, out, nullptr, nullptr, nullptr, nullptr, nullptr, nullptr, x);
}

// round 9
// speedup vs baseline: 1.5205x; 1.0805x over previous
#include <cuda_runtime.h>
#include <cuda_fp16.h>
#include <math.h>
#include <stdint.h>

// ---------------------------------------------------------------------------
// Problem constants
// ---------------------------------------------------------------------------
constexpr int NB   = 16;
constexpr int CH   = 512;
constexpr int NPIX = 1024;
constexpr int NGRP = 32;

// GEMM tiling: CTA 128x128, BK=32, 8 warps (2M x 4N), warp tile 64x32
constexpr int TM = 128, TN = 128, TK = 32;

constexpr int A_STAGE     = 16384;                  // A: 128 rows * 128B (hi|lo)
constexpr int B_STAGE     = 8192;                   // B: 128 rows * 64B (hi only)
constexpr int STAGE_BYTES = A_STAGE + B_STAGE;      // 24576
constexpr int NSTAGE      = 3;
constexpr int SPITCH      = 129;                    // fp32 epilogue pitch
constexpr int SMEM_BYTES  = NSTAGE * STAGE_BYTES;   // 73728 (>= 128*129*4)

// ---------------------------------------------------------------------------
// Scratch (__device__ globals). A-side operands split fp16 (hi+lo, ~22 bit),
// B-side operands single fp16.
// ---------------------------------------------------------------------------
#define BALIGN __align__(256)
__device__ BALIGN __half g_ht [(size_t)NB * NPIX * CH];    // B of QKV
__device__ BALIGN __half g_q_h[(size_t)NB * NPIX * CH];    // A of scores (split)
__device__ BALIGN __half g_q_l[(size_t)NB * NPIX * CH];
__device__ BALIGN __half g_k  [(size_t)NB * NPIX * CH];    // B of scores
__device__ BALIGN __half g_v  [(size_t)NB * CH * NPIX];    // B of PV
__device__ BALIGN __half g_p_h[(size_t)NB * NPIX * NPIX];  // A of PV (split)
__device__ BALIGN __half g_p_l[(size_t)NB * NPIX * NPIX];
__device__ BALIGN __half g_ot [(size_t)NB * NPIX * CH];    // B of proj
__device__ BALIGN __half g_wq_h[(size_t)3 * CH * CH];      // A of QKV (split)
__device__ BALIGN __half g_wq_l[(size_t)3 * CH * CH];
__device__ BALIGN __half g_wp_h[(size_t)CH * CH];          // A of proj (split)
__device__ BALIGN __half g_wp_l[(size_t)CH * CH];
__device__ BALIGN float  g_attn[(size_t)NB * NPIX * NPIX];
__device__ float g_stats[NB * NGRP * 2];

// ---------------------------------------------------------------------------
// helpers
// ---------------------------------------------------------------------------
__device__ __forceinline__ uint32_t smem_u32(const void* p) {
    uint32_t a;
    asm("{ .reg .u64 t; cvta.to.shared.u64 t, %1; cvt.u32.u64 %0, t; }" : "=r"(a) : "l"(p));
    return a;
}
__device__ __forceinline__ void split_f16(float v, __half& h, __half& l) {
    h = __float2half(v);
    l = __float2half(v - __half2float(h));
}

#define CP16(sm, gp) asm volatile("cp.async.cg.shared.global [%0], [%1], 16;" :: "r"(sm), "l"(gp))
#define CP_COMMIT()  asm volatile("cp.async.commit_group;" ::: "memory")
#define CP_WAIT0()   asm volatile("cp.async.wait_group 0;" ::: "memory")
#define CP_WAIT1()   asm volatile("cp.async.wait_group 1;" ::: "memory")

#define LDSM4(r0, r1, r2, r3, a) \
    asm volatile("ldmatrix.sync.aligned.m8n8.x4.shared.b16 {%0,%1,%2,%3}, [%4];" \
                 : "=r"(r0), "=r"(r1), "=r"(r2), "=r"(r3) : "r"(a))

#define MMA_F16(d, a, b0, b1) \
    asm volatile("mma.sync.aligned.m16n8k16.row.col.f32.f16.f16.f32 " \
                 "{%0,%1,%2,%3},{%4,%5,%6,%7},{%8,%9},{%0,%1,%2,%3};" \
                 : "+f"((d)[0]), "+f"((d)[1]), "+f"((d)[2]), "+f"((d)[3]) \
                 : "r"((a)[0]), "r"((a)[1]), "r"((a)[2]), "r"((a)[3]), "r"(b0), "r"(b1))

// ---------------------------------------------------------------------------
// GroupNorm phase 1: per-(b,g) mean / rstd
// ---------------------------------------------------------------------------
__global__ __launch_bounds__(256) void gn_stats_kernel(
    const float* __restrict__ x, float* __restrict__ stats)
{
    const int GSZ = (CH / NGRP) * NPIX;
    const int bg  = blockIdx.x;
    const float4* xv = (const float4*)(x + (size_t)bg * GSZ);
    const int tid = threadIdx.x;

    float s = 0.f, ss = 0.f;
    for (int i = tid; i < GSZ / 4; i += 256) {
        float4 v = xv[i];
        s  += v.x + v.y + v.z + v.w;
        ss += v.x * v.x + v.y * v.y + v.z * v.z + v.w * v.w;
    }
    __shared__ float rs[256], rss[256];
    rs[tid] = s; rss[tid] = ss;
    __syncthreads();
    for (int o = 128; o > 0; o >>= 1) {
        if (tid < o) { rs[tid] += rs[tid + o]; rss[tid] += rss[tid + o]; }
        __syncthreads();
    }
    if (tid == 0) {
        float mu  = rs[0] / GSZ;
        float var = rss[0] / GSZ - mu * mu;
        stats[bg * 2]     = mu;
        stats[bg * 2 + 1] = rsqrtf(var + 1e-5f);
    }
}

// ---------------------------------------------------------------------------
// GroupNorm phase 2: normalize + transpose -> ht[b][p][c] (single fp16)
// ---------------------------------------------------------------------------
__global__ __launch_bounds__(256) void gn_apply_kernel(
    const float* __restrict__ x, const float* __restrict__ gamma,
    const float* __restrict__ beta, const float* __restrict__ stats,
    __half* __restrict__ ht)
{
    __shared__ float s[32][33];
    const int p0 = blockIdx.x * 32, c0 = blockIdx.y * 32, b = blockIdx.z;
    const int tid = threadIdx.x;

    #pragma unroll
    for (int q = 0; q < 4; q++) {
        int ci = (tid >> 5) + q * 8, pj = tid & 31;
        int c = c0 + ci;
        float xv = x[((size_t)b * CH + c) * NPIX + p0 + pj];
        int g = c >> 4;
        float mu = stats[(b * NGRP + g) * 2], rinv = stats[(b * NGRP + g) * 2 + 1];
        s[ci][pj] = (xv - mu) * rinv * gamma[c] + beta[c];
    }
    __syncthreads();
    #pragma unroll
    for (int q = 0; q < 4; q++) {
        int cj = tid & 31, pi = (tid >> 5) + q * 8;
        size_t o = (size_t)b * NPIX * CH + (size_t)(p0 + pi) * CH + c0 + cj;
        ht[o] = __float2half(s[cj][pi]);
    }
}

// ---------------------------------------------------------------------------
// Row softmax -> split-fp16 P
// ---------------------------------------------------------------------------
__global__ __launch_bounds__(256) void softmax_kernel(
    const float* __restrict__ attn,
    __half* __restrict__ ph, __half* __restrict__ pl)
{
    const size_t row = blockIdx.x;
    const float4* p = (const float4*)(attn + row * NPIX);
    const int tid = threadIdx.x;
    const int lane = tid & 31, wrp = tid >> 5;
    __shared__ float red[8];

    float4 v = p[tid];
    float m = fmaxf(fmaxf(v.x, v.y), fmaxf(v.z, v.w));
    #pragma unroll
    for (int o = 16; o > 0; o >>= 1) m = fmaxf(m, __shfl_xor_sync(~0u, m, o));
    if (lane == 0) red[wrp] = m;
    __syncthreads();
    float rmax = red[0];
    #pragma unroll
    for (int w = 1; w < 8; w++) rmax = fmaxf(rmax, red[w]);
    __syncthreads();

    v.x = __expf(v.x - rmax); v.y = __expf(v.y - rmax);
    v.z = __expf(v.z - rmax); v.w = __expf(v.w - rmax);
    float s = v.x + v.y + v.z + v.w;
    #pragma unroll
    for (int o = 16; o > 0; o >>= 1) s += __shfl_xor_sync(~0u, s, o);
    if (lane == 0) red[wrp] = s;
    __syncthreads();
    float tot = red[0];
    #pragma unroll
    for (int w = 1; w < 8; w++) tot += red[w];

    const float rinv = 1.f / tot;
    float vals[4] = {v.x * rinv, v.y * rinv, v.z * rinv, v.w * rinv};
    __half hh[4], ll[4];
    #pragma unroll
    for (int i = 0; i < 4; i++) split_f16(vals[i], hh[i], ll[i]);
    size_t o = row * NPIX + tid * 4;
    *(__half2*)(ph + o)     = __half2(hh[0], hh[1]);
    *(__half2*)(ph + o + 2) = __half2(hh[2], hh[3]);
    *(__half2*)(pl + o)     = __half2(ll[0], ll[1]);
    *(__half2*)(pl + o + 2) = __half2(ll[2], ll[3]);
}

// ---------------------------------------------------------------------------
// fp32 -> split-fp16 (weights)
// ---------------------------------------------------------------------------
__global__ __launch_bounds__(256) void pack_kernel(
    const float* __restrict__ w,
    __half* __restrict__ oh, __half* __restrict__ ol, int n)
{
    int i = (blockIdx.x * 256 + threadIdx.x) * 2;
    if (i < n) {
        __half h0, l0, h1, l1;
        split_f16(w[i], h0, l0);
        split_f16(w[i + 1], h1, l1);
        *(__half2*)(oh + i) = __half2(h0, h1);
        *(__half2*)(ol + i) = __half2(l0, l1);
    }
}

// ---------------------------------------------------------------------------
// 2-term split-fp16 HMMA GEMM: D[m][n] = sum_k A[m][k]*B[n][k] (k-major).
// A = ah + al (fp16 pair), B = bh (single fp16). D = a*bh exactly.
// CTA 128x128, BK=32, 8 warps (2M x 4N), warp tile 64x32, 3-stage cp.async,
// one __syncthreads per k-iter, 2 CTAs/SM.
// A smem row 128B [hi|lo] swz u^(row&7); B smem row 64B swz u^((row>>1)&3).
// EPI 0: QKV  1: scores  2: PV  3: proj(+bias+residual)
// ---------------------------------------------------------------------------
template<int EPI>
__global__ __launch_bounds__(256, 2) void tc_gemm(
    const __half* __restrict__ Agh, const __half* __restrict__ Agl,
    const __half* __restrict__ Bg,
    long long sAb, long long sBb, int ldA, int ldB, int K,
    const float* __restrict__ bias, float scale,
    float* __restrict__ outf,
    __half* __restrict__ o0h, __half* __restrict__ o0l,
    __half* __restrict__ o1, __half* __restrict__ o2,
    const float* __restrict__ resid)
{
    extern __shared__ char smem[];
    const uint32_t sb = smem_u32(smem);
    const int tid = threadIdx.x;
    const int lane = tid & 31, wid = tid >> 5;
    const int bz = blockIdx.z;
    const int m0 = blockIdx.y * TM;
    const int n0 = blockIdx.x * TN;

    const __half* Ah = Agh + (size_t)bz * sAb + (size_t)m0 * ldA;
    const __half* Al = Agl + (size_t)bz * sAb + (size_t)m0 * ldA;
    const __half* Bp = Bg  + (size_t)bz * sBb + (size_t)n0 * ldB;

    // loaders: row = tid>>1; A: 4 units (hi for even tid, lo for odd); B: 2 units
    const int lrow = tid >> 1;
    const int asel = tid & 1;

    auto load_tile = [&](int buf, int k0) {
        const uint32_t sa  = sb + buf * STAGE_BYTES;
        const uint32_t sbB = sa + A_STAGE;
        const __half* Asrc = asel ? Al : Ah;
        #pragma unroll
        for (int j = 0; j < 4; j++) {
            const int u = asel * 4 + j;
            CP16(sa + lrow * 128 + ((u ^ (lrow & 7)) << 4),
                 Asrc + (size_t)lrow * ldA + k0 + j * 8);
        }
        #pragma unroll
        for (int j = 0; j < 2; j++) {
            const int u = asel * 2 + j;
            CP16(sbB + lrow * 64 + ((u ^ ((lrow >> 1) & 3)) << 4),
                 Bp + (size_t)lrow * ldB + k0 + u * 8);
        }
    };

    // warp layout: 2 (M) x 4 (N), warp tile 64x32
    const int wm = wid >> 2, wn = wid & 3;
    const int m_base = wm * 64, n_base = wn * 32;

    // ldmatrix lane mapping
    const int amat = lane >> 3;
    const int arow = (amat & 1) * 8 + (lane & 7);
    const int auadd = amat >> 1;
    const int bmat = lane >> 3;
    const int bnrow = (bmat >> 1) * 8 + (lane & 7);
    const int buadd = bmat & 1;

    float acc[4][4][4] = {};

    load_tile(0, 0);
    CP_COMMIT();
    load_tile(1, TK);
    CP_COMMIT();

    const int nk = K / TK;
    for (int i = 0; i < nk; i++) {
        if (i == nk - 1) { CP_WAIT0(); } else { CP_WAIT1(); }
        __syncthreads();
        if (i + 2 < nk) {
            load_tile((i + 2) % NSTAGE, (i + 2) * TK);
            CP_COMMIT();
        }
        const uint32_t sa  = sb + (i % NSTAGE) * STAGE_BYTES;
        const uint32_t sbB = sa + A_STAGE;

        #pragma unroll
        for (int kk = 0; kk < 2; kk++) {
            // B fragments (hi only, 8 regs)
            uint32_t bh[8];
            #pragma unroll
            for (int np = 0; np < 2; np++) {
                const int n = n_base + np * 16 + bnrow;
                const uint32_t base = sbB + n * 64;
                const int uh = kk * 2 + buadd;
                LDSM4(bh[np * 4 + 0], bh[np * 4 + 1], bh[np * 4 + 2], bh[np * 4 + 3],
                      base + ((uh ^ ((n >> 1) & 3)) << 4));
            }
            // A fragments in 2 chunks of 2 mt; 2 terms per accumulator
            #pragma unroll
            for (int mc = 0; mc < 2; mc++) {
                uint32_t ah[2][4], al[2][4];
                #pragma unroll
                for (int m2 = 0; m2 < 2; m2++) {
                    const int mt = mc * 2 + m2;
                    const int row = m_base + mt * 16 + arow;
                    const int rx = row & 7;
                    const uint32_t base = sa + row * 128;
                    const int uh = kk * 2 + auadd;
                    LDSM4(ah[m2][0], ah[m2][1], ah[m2][2], ah[m2][3],
                          base + ((uh ^ rx) << 4));
                    LDSM4(al[m2][0], al[m2][1], al[m2][2], al[m2][3],
                          base + (((uh + 4) ^ rx) << 4));
                }
                // term 0: ah x bh
                #pragma unroll
                for (int m2 = 0; m2 < 2; m2++)
                    #pragma unroll
                    for (int nt = 0; nt < 4; nt++) {
                        const int r = (nt >> 1) * 4 + (nt & 1) * 2;
                        MMA_F16(acc[mc * 2 + m2][nt], ah[m2], bh[r], bh[r + 1]);
                    }
                // term 1: al x bh
                #pragma unroll
                for (int m2 = 0; m2 < 2; m2++)
                    #pragma unroll
                    for (int nt = 0; nt < 4; nt++) {
                        const int r = (nt >> 1) * 4 + (nt & 1) * 2;
                        MMA_F16(acc[mc * 2 + m2][nt], al[m2], bh[r], bh[r + 1]);
                    }
            }
        }
    }

    // ---- stage accumulators to smem fp32 (reuse pipeline smem) ----
    __syncthreads();
    float* s = (float*)smem;
    #pragma unroll
    for (int mt = 0; mt < 4; mt++)
        #pragma unroll
        for (int nt = 0; nt < 4; nt++)
            #pragma unroll
            for (int r = 0; r < 4; r++) {
                const int row = m_base + mt * 16 + (lane >> 2) + (r >= 2 ? 8 : 0);
                const int col = n_base + nt * 8 + (lane & 3) * 2 + (r & 1);
                s[row * SPITCH + col] = acc[mt][nt][r];
            }
    __syncthreads();

    // ---- writers ----
    if (EPI == 0 && m0 < CH) {
        // Q tile: split store [p][c], m-fast pairs coalesced over c
        __half* dh = o0h + (size_t)bz * NPIX * CH;
        __half* dl = o0l + (size_t)bz * NPIX * CH;
        for (int it = 0; it < 32; it++) {
            const int idx = it * 512 + tid * 2;
            const int n = idx >> 7, m = idx & 127;
            float v0 = s[m * SPITCH + n] + bias[m0 + m];
            float v1 = s[(m + 1) * SPITCH + n] + bias[m0 + m + 1];
            __half h0, l0, h1, l1;
            split_f16(v0, h0, l0); split_f16(v1, h1, l1);
            const size_t o = (size_t)(n0 + n) * CH + m0 + m;
            *(__half2*)(dh + o) = __half2(h0, h1);
            *(__half2*)(dl + o) = __half2(l0, l1);
        }
    } else if (EPI == 0 && m0 < 2 * CH) {
        // K tile: single fp16 store [p][c]
        __half* dk = o1 + (size_t)bz * NPIX * CH;
        const int coff = m0 - CH;
        for (int it = 0; it < 32; it++) {
            const int idx = it * 512 + tid * 2;
            const int n = idx >> 7, m = idx & 127;
            float v0 = s[m * SPITCH + n] + bias[m0 + m];
            float v1 = s[(m + 1) * SPITCH + n] + bias[m0 + m + 1];
            const size_t o = (size_t)(n0 + n) * CH + coff + m;
            *(__half2*)(dk + o) = __half2(__float2half(v0), __float2half(v1));
        }
    } else {
        for (int it = 0; it < 32; it++) {
            const int idx = it * 512 + tid * 2;
            const int m = idx >> 7, n = idx & 127;
            float v0 = s[m * SPITCH + n];
            float v1 = s[m * SPITCH + n + 1];
            if (EPI == 0) {          // V tile -> v[b][c][p] single fp16
                const int c = m0 - 2 * CH + m;
                v0 += bias[m0 + m]; v1 += bias[m0 + m];
                const size_t o = ((size_t)bz * CH + c) * NPIX + n0 + n;
                *(__half2*)(o2 + o) = __half2(__float2half(v0), __float2half(v1));
            } else if (EPI == 1) {   // scores fp32
                const size_t o = ((size_t)bz * NPIX + m0 + m) * NPIX + n0 + n;
                *(float2*)(outf + o) = make_float2(v0 * scale, v1 * scale);
            } else if (EPI == 2) {   // Ot single fp16 [p][c]
                const size_t o = ((size_t)bz * NPIX + m0 + m) * CH + n0 + n;
                *(__half2*)(o0h + o) = __half2(__float2half(v0), __float2half(v1));
            } else {                 // proj + bias + residual
                const float bv = bias[m0 + m];
                const size_t o = ((size_t)bz * CH + m0 + m) * NPIX + n0 + n;
                float2 rv = *(const float2*)(resid + o);
                *(float2*)(outf + o) = make_float2(v0 + bv + rv.x, v1 + bv + rv.y);
            }
        }
    }
}

// ---------------------------------------------------------------------------
extern "C" void kernel_launch(void* const* d_in, const int* in_sizes, int n_in,
                              void* d_out, int out_size)
{
    const float* x      = (const float*)d_in[0];
    const float* gamma  = (const float*)d_in[1];
    const float* beta   = (const float*)d_in[2];
    const float* w_qkv  = (const float*)d_in[3];
    const float* b_qkv  = (const float*)d_in[4];
    const float* w_proj = (const float*)d_in[5];
    const float* b_proj = (const float*)d_in[6];
    float* out = (float*)d_out;

    __half *ht, *qh, *ql, *kk, *vv, *ph, *pl, *ot, *wqh, *wql, *wph, *wpl;
    float *attn, *stats;
    cudaGetSymbolAddress((void**)&ht,  g_ht );
    cudaGetSymbolAddress((void**)&qh,  g_q_h); cudaGetSymbolAddress((void**)&ql, g_q_l);
    cudaGetSymbolAddress((void**)&kk,  g_k  );
    cudaGetSymbolAddress((void**)&vv,  g_v  );
    cudaGetSymbolAddress((void**)&ph,  g_p_h); cudaGetSymbolAddress((void**)&pl, g_p_l);
    cudaGetSymbolAddress((void**)&ot,  g_ot );
    cudaGetSymbolAddress((void**)&wqh, g_wq_h); cudaGetSymbolAddress((void**)&wql, g_wq_l);
    cudaGetSymbolAddress((void**)&wph, g_wp_h); cudaGetSymbolAddress((void**)&wpl, g_wp_l);
    cudaGetSymbolAddress((void**)&attn, g_attn);
    cudaGetSymbolAddress((void**)&stats, g_stats);

    cudaFuncSetAttribute(tc_gemm<0>, cudaFuncAttributeMaxDynamicSharedMemorySize, SMEM_BYTES);
    cudaFuncSetAttribute(tc_gemm<1>, cudaFuncAttributeMaxDynamicSharedMemorySize, SMEM_BYTES);
    cudaFuncSetAttribute(tc_gemm<2>, cudaFuncAttributeMaxDynamicSharedMemorySize, SMEM_BYTES);
    cudaFuncSetAttribute(tc_gemm<3>, cudaFuncAttributeMaxDynamicSharedMemorySize, SMEM_BYTES);

    const long long sH = (long long)NPIX * CH;
    const long long sP = (long long)NPIX * NPIX;

    pack_kernel<<<(3 * CH * CH / 2 + 255) / 256, 256>>>(w_qkv, wqh, wql, 3 * CH * CH);
    pack_kernel<<<(CH * CH / 2 + 255) / 256, 256>>>(w_proj, wph, wpl, CH * CH);
    gn_stats_kernel<<<NB * NGRP, 256>>>(x, stats);
    gn_apply_kernel<<<dim3(NPIX / 32, CH / 32, NB), 256>>>(x, gamma, beta, stats, ht);

    // QKV: A = w_qkv split, B = ht single -> q split [p][c], k single, v single [c][p]
    tc_gemm<0><<<dim3(NPIX / TN, 1536 / TM, NB), 256, SMEM_BYTES>>>(
        wqh, wql, ht, 0, sH, CH, CH, CH,
        b_qkv, 1.f, nullptr, qh, ql, kk, vv, nullptr);

    // scores: A = q split, B = k single -> attn fp32
    tc_gemm<1><<<dim3(NPIX / TN, NPIX / TM, NB), 256, SMEM_BYTES>>>(
        qh, ql, kk, sH, sH, CH, CH, CH,
        nullptr, 1.0f / sqrtf((float)CH), attn,
        nullptr, nullptr, nullptr, nullptr, nullptr);

    softmax_kernel<<<NB * NPIX, 256>>>(attn, ph, pl);

    // PV: A = p split, B = v single -> ot single [p][c]
    tc_gemm<2><<<dim3(CH / TN, NPIX / TM, NB), 256, SMEM_BYTES>>>(
        ph, pl, vv, sP, sH, NPIX, NPIX, NPIX,
        nullptr, 1.f, nullptr, ot, nullptr, nullptr, nullptr, nullptr);

    // proj: A = w_proj split, B = ot single + bias + residual -> out fp32
    tc_gemm<3><<<dim3(NPIX / TN, CH / TM, NB), 256, SMEM_BYTES>>>(
        wph, wpl, ot, 0, sH, CH, CH, CH,
        b_proj, 1.f, out, nullptr, nullptr, nullptr, nullptr, x);
}

// round 10
// speedup vs baseline: 2.8480x; 1.8730x over previous
#include <cuda_runtime.h>
#include <cuda_fp16.h>
#include <math.h>
#include <stdint.h>

// ---------------------------------------------------------------------------
// Problem constants
// ---------------------------------------------------------------------------
constexpr int NB   = 16;
constexpr int CH   = 512;
constexpr int NPIX = 1024;
constexpr int NGRP = 32;

// GEMM tiling: CTA 128x128, BK=32, 8 warps (2M x 4N), warp tile 64x32
constexpr int TM = 128, TN = 128, TK = 32;

constexpr int A_STAGE     = 8192;                   // A: 128 rows * 64B
constexpr int B_STAGE     = 8192;                   // B: 128 rows * 64B
constexpr int STAGE_BYTES = A_STAGE + B_STAGE;      // 16384
constexpr int NSTAGE      = 3;                      // 49152 B of stages
constexpr int SPITCH      = 129;                    // fp32 epilogue pitch
constexpr int SMEM_BYTES  = TM * SPITCH * 4;        // 66048 (> 3*16384)

// ---------------------------------------------------------------------------
// Scratch (__device__ globals). All GEMM operands single fp16.
// ---------------------------------------------------------------------------
#define BALIGN __align__(256)
__device__ BALIGN __half g_ht[(size_t)NB * NPIX * CH];    // B of QKV   [b][p][c]
__device__ BALIGN __half g_q [(size_t)NB * NPIX * CH];    // A of scores[b][p][c]
__device__ BALIGN __half g_k [(size_t)NB * NPIX * CH];    // B of scores[b][p][c]
__device__ BALIGN __half g_v [(size_t)NB * CH * NPIX];    // B of PV    [b][c][p]
__device__ BALIGN __half g_p [(size_t)NB * NPIX * NPIX];  // A of PV    [b][i][j]
__device__ BALIGN __half g_ot[(size_t)NB * NPIX * CH];    // B of proj  [b][p][c]
__device__ BALIGN __half g_wq[(size_t)3 * CH * CH];       // A of QKV
__device__ BALIGN __half g_wp[(size_t)CH * CH];           // A of proj
__device__ BALIGN float  g_attn[(size_t)NB * NPIX * NPIX];
__device__ float g_stats[NB * NGRP * 2];

// ---------------------------------------------------------------------------
// helpers
// ---------------------------------------------------------------------------
__device__ __forceinline__ uint32_t smem_u32(const void* p) {
    uint32_t a;
    asm("{ .reg .u64 t; cvta.to.shared.u64 t, %1; cvt.u32.u64 %0, t; }" : "=r"(a) : "l"(p));
    return a;
}

#define CP16(sm, gp) asm volatile("cp.async.cg.shared.global [%0], [%1], 16;" :: "r"(sm), "l"(gp))
#define CP_COMMIT()  asm volatile("cp.async.commit_group;" ::: "memory")
#define CP_WAIT0()   asm volatile("cp.async.wait_group 0;" ::: "memory")
#define CP_WAIT1()   asm volatile("cp.async.wait_group 1;" ::: "memory")

#define LDSM4(r0, r1, r2, r3, a) \
    asm volatile("ldmatrix.sync.aligned.m8n8.x4.shared.b16 {%0,%1,%2,%3}, [%4];" \
                 : "=r"(r0), "=r"(r1), "=r"(r2), "=r"(r3) : "r"(a))

#define MMA_F16(d, a, b0, b1) \
    asm volatile("mma.sync.aligned.m16n8k16.row.col.f32.f16.f16.f32 " \
                 "{%0,%1,%2,%3},{%4,%5,%6,%7},{%8,%9},{%0,%1,%2,%3};" \
                 : "+f"((d)[0]), "+f"((d)[1]), "+f"((d)[2]), "+f"((d)[3]) \
                 : "r"((a)[0]), "r"((a)[1]), "r"((a)[2]), "r"((a)[3]), "r"(b0), "r"(b1))

// ---------------------------------------------------------------------------
// GroupNorm phase 1: per-(b,g) mean / rstd
// ---------------------------------------------------------------------------
__global__ __launch_bounds__(256) void gn_stats_kernel(
    const float* __restrict__ x, float* __restrict__ stats)
{
    const int GSZ = (CH / NGRP) * NPIX;
    const int bg  = blockIdx.x;
    const float4* xv = (const float4*)(x + (size_t)bg * GSZ);
    const int tid = threadIdx.x;

    float s = 0.f, ss = 0.f;
    for (int i = tid; i < GSZ / 4; i += 256) {
        float4 v = xv[i];
        s  += v.x + v.y + v.z + v.w;
        ss += v.x * v.x + v.y * v.y + v.z * v.z + v.w * v.w;
    }
    __shared__ float rs[256], rss[256];
    rs[tid] = s; rss[tid] = ss;
    __syncthreads();
    for (int o = 128; o > 0; o >>= 1) {
        if (tid < o) { rs[tid] += rs[tid + o]; rss[tid] += rss[tid + o]; }
        __syncthreads();
    }
    if (tid == 0) {
        float mu  = rs[0] / GSZ;
        float var = rss[0] / GSZ - mu * mu;
        stats[bg * 2]     = mu;
        stats[bg * 2 + 1] = rsqrtf(var + 1e-5f);
    }
}

// ---------------------------------------------------------------------------
// GroupNorm phase 2: normalize + transpose -> ht[b][p][c] (fp16)
// ---------------------------------------------------------------------------
__global__ __launch_bounds__(256) void gn_apply_kernel(
    const float* __restrict__ x, const float* __restrict__ gamma,
    const float* __restrict__ beta, const float* __restrict__ stats,
    __half* __restrict__ ht)
{
    __shared__ float s[32][33];
    const int p0 = blockIdx.x * 32, c0 = blockIdx.y * 32, b = blockIdx.z;
    const int tid = threadIdx.x;

    #pragma unroll
    for (int q = 0; q < 4; q++) {
        int ci = (tid >> 5) + q * 8, pj = tid & 31;
        int c = c0 + ci;
        float xv = x[((size_t)b * CH + c) * NPIX + p0 + pj];
        int g = c >> 4;
        float mu = stats[(b * NGRP + g) * 2], rinv = stats[(b * NGRP + g) * 2 + 1];
        s[ci][pj] = (xv - mu) * rinv * gamma[c] + beta[c];
    }
    __syncthreads();
    #pragma unroll
    for (int q = 0; q < 4; q++) {
        int cj = tid & 31, pi = (tid >> 5) + q * 8;
        size_t o = (size_t)b * NPIX * CH + (size_t)(p0 + pi) * CH + c0 + cj;
        ht[o] = __float2half(s[cj][pi]);
    }
}

// ---------------------------------------------------------------------------
// Row softmax -> fp16 P
// ---------------------------------------------------------------------------
__global__ __launch_bounds__(256) void softmax_kernel(
    const float* __restrict__ attn, __half* __restrict__ ph)
{
    const size_t row = blockIdx.x;
    const float4* p = (const float4*)(attn + row * NPIX);
    const int tid = threadIdx.x;
    const int lane = tid & 31, wrp = tid >> 5;
    __shared__ float red[8];

    float4 v = p[tid];
    float m = fmaxf(fmaxf(v.x, v.y), fmaxf(v.z, v.w));
    #pragma unroll
    for (int o = 16; o > 0; o >>= 1) m = fmaxf(m, __shfl_xor_sync(~0u, m, o));
    if (lane == 0) red[wrp] = m;
    __syncthreads();
    float rmax = red[0];
    #pragma unroll
    for (int w = 1; w < 8; w++) rmax = fmaxf(rmax, red[w]);
    __syncthreads();

    v.x = __expf(v.x - rmax); v.y = __expf(v.y - rmax);
    v.z = __expf(v.z - rmax); v.w = __expf(v.w - rmax);
    float s = v.x + v.y + v.z + v.w;
    #pragma unroll
    for (int o = 16; o > 0; o >>= 1) s += __shfl_xor_sync(~0u, s, o);
    if (lane == 0) red[wrp] = s;
    __syncthreads();
    float tot = red[0];
    #pragma unroll
    for (int w = 1; w < 8; w++) tot += red[w];

    const float rinv = 1.f / tot;
    size_t o = row * NPIX + tid * 4;
    *(__half2*)(ph + o)     = __half2(__float2half(v.x * rinv), __float2half(v.y * rinv));
    *(__half2*)(ph + o + 2) = __half2(__float2half(v.z * rinv), __float2half(v.w * rinv));
}

// ---------------------------------------------------------------------------
// fp32 -> fp16 (weights)
// ---------------------------------------------------------------------------
__global__ __launch_bounds__(256) void pack_kernel(
    const float* __restrict__ w, __half* __restrict__ o, int n)
{
    int i = (blockIdx.x * 256 + threadIdx.x) * 2;
    if (i < n) {
        *(__half2*)(o + i) = __half2(__float2half(w[i]), __float2half(w[i + 1]));
    }
}

// ---------------------------------------------------------------------------
// fp16 HMMA GEMM: D[m][n] = sum_k A[m][k]*B[n][k] (both k-major, fp16).
// CTA 128x128, BK=32, 8 warps (2M x 4N), warp tile 64x32, 3-stage cp.async,
// one __syncthreads per k-iter, 2 CTAs/SM.
// smem rows 64B, 16B units XOR-swizzled by (row>>1)&3.
// EPI 0: QKV  1: scores  2: PV  3: proj(+bias+residual)
// ---------------------------------------------------------------------------
template<int EPI>
__global__ __launch_bounds__(256, 2) void tc_gemm(
    const __half* __restrict__ Ag, const __half* __restrict__ Bg,
    long long sAb, long long sBb, int ldA, int ldB, int K,
    const float* __restrict__ bias, float scale,
    float* __restrict__ outf,
    __half* __restrict__ o0, __half* __restrict__ o1, __half* __restrict__ o2,
    const float* __restrict__ resid)
{
    extern __shared__ char smem[];
    const uint32_t sb = smem_u32(smem);
    const int tid = threadIdx.x;
    const int lane = tid & 31, wid = tid >> 5;
    const int bz = blockIdx.z;
    const int m0 = blockIdx.y * TM;
    const int n0 = blockIdx.x * TN;

    const __half* Ap = Ag + (size_t)bz * sAb + (size_t)m0 * ldA;
    const __half* Bp = Bg + (size_t)bz * sBb + (size_t)n0 * ldB;

    // loaders: row = tid>>1 (0..127), 2 of 4 16B units each
    const int lrow = tid >> 1;
    const int usel = tid & 1;

    auto load_tile = [&](int buf, int k0) {
        const uint32_t sa  = sb + buf * STAGE_BYTES;
        const uint32_t sbB = sa + A_STAGE;
        const int rsw = (lrow >> 1) & 3;
        #pragma unroll
        for (int j = 0; j < 2; j++) {
            const int u = usel * 2 + j;
            const uint32_t sw = (uint32_t)((u ^ rsw) << 4);
            CP16(sa  + lrow * 64 + sw, Ap + (size_t)lrow * ldA + k0 + u * 8);
            CP16(sbB + lrow * 64 + sw, Bp + (size_t)lrow * ldB + k0 + u * 8);
        }
    };

    // warp layout: 2 (M) x 4 (N), warp tile 64x32
    const int wm = wid >> 2, wn = wid & 3;
    const int m_base = wm * 64, n_base = wn * 32;

    // ldmatrix lane mapping
    const int amat = lane >> 3;
    const int arow = (amat & 1) * 8 + (lane & 7);
    const int auadd = amat >> 1;
    const int bmat = lane >> 3;
    const int bnrow = (bmat >> 1) * 8 + (lane & 7);
    const int buadd = bmat & 1;

    float acc[4][4][4] = {};

    load_tile(0, 0);
    CP_COMMIT();
    load_tile(1, TK);
    CP_COMMIT();

    const int nk = K / TK;
    for (int i = 0; i < nk; i++) {
        if (i == nk - 1) { CP_WAIT0(); } else { CP_WAIT1(); }
        __syncthreads();
        if (i + 2 < nk) {
            load_tile((i + 2) % NSTAGE, (i + 2) * TK);
            CP_COMMIT();
        }
        const uint32_t sa  = sb + (i % NSTAGE) * STAGE_BYTES;
        const uint32_t sbB = sa + A_STAGE;

        #pragma unroll
        for (int kk = 0; kk < 2; kk++) {
            uint32_t bh[8];
            #pragma unroll
            for (int np = 0; np < 2; np++) {
                const int n = n_base + np * 16 + bnrow;
                const int uh = kk * 2 + buadd;
                LDSM4(bh[np * 4 + 0], bh[np * 4 + 1], bh[np * 4 + 2], bh[np * 4 + 3],
                      sbB + n * 64 + ((uh ^ ((n >> 1) & 3)) << 4));
            }
            uint32_t ah[4][4];
            #pragma unroll
            for (int mt = 0; mt < 4; mt++) {
                const int row = m_base + mt * 16 + arow;
                const int uh = kk * 2 + auadd;
                LDSM4(ah[mt][0], ah[mt][1], ah[mt][2], ah[mt][3],
                      sa + row * 64 + ((uh ^ ((row >> 1) & 3)) << 4));
            }
            // 16 MMAs, each accumulator touched exactly once per kk
            #pragma unroll
            for (int mt = 0; mt < 4; mt++)
                #pragma unroll
                for (int nt = 0; nt < 4; nt++) {
                    const int r = (nt >> 1) * 4 + (nt & 1) * 2;
                    MMA_F16(acc[mt][nt], ah[mt], bh[r], bh[r + 1]);
                }
        }
    }

    // ---- stage accumulators to smem fp32 (reuse pipeline smem) ----
    __syncthreads();
    float* s = (float*)smem;
    #pragma unroll
    for (int mt = 0; mt < 4; mt++)
        #pragma unroll
        for (int nt = 0; nt < 4; nt++)
            #pragma unroll
            for (int r = 0; r < 4; r++) {
                const int row = m_base + mt * 16 + (lane >> 2) + (r >= 2 ? 8 : 0);
                const int col = n_base + nt * 8 + (lane & 3) * 2 + (r & 1);
                s[row * SPITCH + col] = acc[mt][nt][r];
            }
    __syncthreads();

    // ---- writers ----
    if (EPI == 0 && m0 < 2 * CH) {
        // Q or K tile: fp16 store [p][c], m-fast pairs coalesced over c
        __half* d = (m0 < CH ? o0 : o1) + (size_t)bz * NPIX * CH;
        const int coff = m0 & (CH - 1);
        for (int it = 0; it < 32; it++) {
            const int idx = it * 512 + tid * 2;
            const int n = idx >> 7, m = idx & 127;
            float v0 = s[m * SPITCH + n] + bias[m0 + m];
            float v1 = s[(m + 1) * SPITCH + n] + bias[m0 + m + 1];
            const size_t o = (size_t)(n0 + n) * CH + coff + m;
            *(__half2*)(d + o) = __half2(__float2half(v0), __float2half(v1));
        }
    } else {
        for (int it = 0; it < 32; it++) {
            const int idx = it * 512 + tid * 2;
            const int m = idx >> 7, n = idx & 127;
            float v0 = s[m * SPITCH + n];
            float v1 = s[m * SPITCH + n + 1];
            if (EPI == 0) {          // V tile -> v[b][c][p] fp16
                const int c = m0 - 2 * CH + m;
                v0 += bias[m0 + m]; v1 += bias[m0 + m];
                const size_t o = ((size_t)bz * CH + c) * NPIX + n0 + n;
                *(__half2*)(o2 + o) = __half2(__float2half(v0), __float2half(v1));
            } else if (EPI == 1) {   // scores fp32
                const size_t o = ((size_t)bz * NPIX + m0 + m) * NPIX + n0 + n;
                *(float2*)(outf + o) = make_float2(v0 * scale, v1 * scale);
            } else if (EPI == 2) {   // Ot fp16 [p][c]
                const size_t o = ((size_t)bz * NPIX + m0 + m) * CH + n0 + n;
                *(__half2*)(o0 + o) = __half2(__float2half(v0), __float2half(v1));
            } else {                 // proj + bias + residual
                const float bv = bias[m0 + m];
                const size_t o = ((size_t)bz * CH + m0 + m) * NPIX + n0 + n;
                float2 rv = *(const float2*)(resid + o);
                *(float2*)(outf + o) = make_float2(v0 + bv + rv.x, v1 + bv + rv.y);
            }
        }
    }
}

// ---------------------------------------------------------------------------
extern "C" void kernel_launch(void* const* d_in, const int* in_sizes, int n_in,
                              void* d_out, int out_size)
{
    const float* x      = (const float*)d_in[0];
    const float* gamma  = (const float*)d_in[1];
    const float* beta   = (const float*)d_in[2];
    const float* w_qkv  = (const float*)d_in[3];
    const float* b_qkv  = (const float*)d_in[4];
    const float* w_proj = (const float*)d_in[5];
    const float* b_proj = (const float*)d_in[6];
    float* out = (float*)d_out;

    __half *ht, *qq, *kk, *vv, *pp, *ot, *wq, *wp;
    float *attn, *stats;
    cudaGetSymbolAddress((void**)&ht, g_ht);
    cudaGetSymbolAddress((void**)&qq, g_q );
    cudaGetSymbolAddress((void**)&kk, g_k );
    cudaGetSymbolAddress((void**)&vv, g_v );
    cudaGetSymbolAddress((void**)&pp, g_p );
    cudaGetSymbolAddress((void**)&ot, g_ot);
    cudaGetSymbolAddress((void**)&wq, g_wq);
    cudaGetSymbolAddress((void**)&wp, g_wp);
    cudaGetSymbolAddress((void**)&attn, g_attn);
    cudaGetSymbolAddress((void**)&stats, g_stats);

    cudaFuncSetAttribute(tc_gemm<0>, cudaFuncAttributeMaxDynamicSharedMemorySize, SMEM_BYTES);
    cudaFuncSetAttribute(tc_gemm<1>, cudaFuncAttributeMaxDynamicSharedMemorySize, SMEM_BYTES);
    cudaFuncSetAttribute(tc_gemm<2>, cudaFuncAttributeMaxDynamicSharedMemorySize, SMEM_BYTES);
    cudaFuncSetAttribute(tc_gemm<3>, cudaFuncAttributeMaxDynamicSharedMemorySize, SMEM_BYTES);

    const long long sH = (long long)NPIX * CH;
    const long long sP = (long long)NPIX * NPIX;

    pack_kernel<<<(3 * CH * CH / 2 + 255) / 256, 256>>>(w_qkv, wq, 3 * CH * CH);
    pack_kernel<<<(CH * CH / 2 + 255) / 256, 256>>>(w_proj, wp, CH * CH);
    gn_stats_kernel<<<NB * NGRP, 256>>>(x, stats);
    gn_apply_kernel<<<dim3(NPIX / 32, CH / 32, NB), 256>>>(x, gamma, beta, stats, ht);

    // QKV: A = w_qkv, B = ht -> q [p][c], k [p][c], v [c][p]
    tc_gemm<0><<<dim3(NPIX / TN, 1536 / TM, NB), 256, SMEM_BYTES>>>(
        wq, ht, 0, sH, CH, CH, CH,
        b_qkv, 1.f, nullptr, qq, kk, vv, nullptr);

    // scores: A = q, B = k -> attn fp32
    tc_gemm<1><<<dim3(NPIX / TN, NPIX / TM, NB), 256, SMEM_BYTES>>>(
        qq, kk, sH, sH, CH, CH, CH,
        nullptr, 1.0f / sqrtf((float)CH), attn,
        nullptr, nullptr, nullptr, nullptr);

    softmax_kernel<<<NB * NPIX, 256>>>(attn, pp);

    // PV: A = p, B = v -> ot [p][c]
    tc_gemm<2><<<dim3(CH / TN, NPIX / TM, NB), 256, SMEM_BYTES>>>(
        pp, vv, sP, sH, NPIX, NPIX, NPIX,
        nullptr, 1.f, nullptr, ot, nullptr, nullptr, nullptr);

    // proj: A = w_proj, B = ot + bias + residual -> out fp32
    tc_gemm<3><<<dim3(NPIX / TN, CH / TM, NB), 256, SMEM_BYTES>>>(
        wp, ot, 0, sH, CH, CH, CH,
        b_proj, 1.f, out, nullptr, nullptr, nullptr, x);
}